// round 15
// baseline (speedup 1.0000x reference)
#include <cuda_runtime.h>
#include <cuda_bf16.h>
#include <math.h>
#include <stdint.h>

#define Bb   2
#define Ls   2048
#define Dm   512
#define Hh   8
#define HDim 64
#define LcC  512
#define NSEL 8
#define NJT  16

// ---------------- side stream for MLP-branch overlap (created pre-main) ----------------
static cudaStream_t g_s2;
static cudaEvent_t  g_evA, g_evB;
struct GStreamInit {
    GStreamInit() {
        cudaStreamCreateWithFlags(&g_s2, cudaStreamNonBlocking);
        cudaEventCreateWithFlags(&g_evA, cudaEventDisableTiming);
        cudaEventCreateWithFlags(&g_evB, cudaEventDisableTiming);
    }
};
static GStreamInit g_stream_init;

// ---------------- fp32 scratch ----------------
static __device__ float g_q[Bb*Ls*Dm];
static __device__ float g_k[Bb*Ls*Dm];
static __device__ float g_v[Bb*Ls*Dm];
static __device__ float g_outg[Bb*Ls*Dm];
static __device__ float g_outl[Bb*Ls*Dm];
static __device__ float g_comb[Bb*Ls*Dm];
static __device__ float g_imp[Bb*Hh*Ls];
static __device__ int   g_selidx[Bb*Hh*NSEL];
static __device__ float g_pmax[Bb*Hh*Ls*NJT];
static __device__ float g_pse [Bb*Hh*Ls*NJT];
static __device__ float g_psum[Bb*Hh*Ls*NJT];

// ---------------- bf16 split scratch ----------------
static __device__ __nv_bfloat16 g_wth[6][Dm*Dm];   // transposed [N][K]
static __device__ __nv_bfloat16 g_wtl[6][Dm*Dm];
static __device__ __nv_bfloat16 g_qh[Bb*Ls*Dm], g_ql[Bb*Ls*Dm];
static __device__ __nv_bfloat16 g_kh[Bb*Ls*Dm], g_kl[Bb*Ls*Dm];
static __device__ __nv_bfloat16 g_vh[Bb*Ls*Dm], g_vl[Bb*Ls*Dm];
static __device__ __nv_bfloat16 g_kch[Bb*LcC*Dm], g_kcl[Bb*LcC*Dm];
static __device__ __nv_bfloat16 g_vch[Bb*LcC*Dm], g_vcl[Bb*LcC*Dm];
static __device__ __nv_bfloat16 g_kcpreh[Bb*LcC*Dm], g_kcprel[Bb*LcC*Dm];
static __device__ __nv_bfloat16 g_hidh[Bb*LcC*Dm], g_hidl[Bb*LcC*Dm];
static __device__ __nv_bfloat16 g_combh[Bb*Ls*Dm], g_combl[Bb*Ls*Dm];

__device__ __forceinline__ void bsplit(float x, __nv_bfloat16& h, __nv_bfloat16& l)
{
    h = __float2bfloat16(x);
    l = __float2bfloat16(x - __bfloat162float(h));
}

__device__ __forceinline__ uint32_t packbf(float x, float y)
{
    __nv_bfloat162 t = __floats2bfloat162_rn(x, y);
    return *(uint32_t*)&t;
}

__device__ __forceinline__ void split2(float a, float b, uint32_t& h2, uint32_t& l2)
{
    __nv_bfloat16 ha = __float2bfloat16(a), hb = __float2bfloat16(b);
    float la = a - __bfloat162float(ha), lb = b - __bfloat162float(hb);
    __nv_bfloat162 hp; hp.x = ha; hp.y = hb;
    h2 = *(uint32_t*)&hp;
    l2 = packbf(la, lb);
}

__device__ __forceinline__ void mma16816(float* c, const uint32_t* a, const uint32_t* b)
{
    asm volatile(
        "mma.sync.aligned.m16n8k16.row.col.f32.bf16.bf16.f32 "
        "{%0,%1,%2,%3}, {%4,%5,%6,%7}, {%8,%9}, {%0,%1,%2,%3};"
        : "+f"(c[0]), "+f"(c[1]), "+f"(c[2]), "+f"(c[3])
        : "r"(a[0]), "r"(a[1]), "r"(a[2]), "r"(a[3]), "r"(b[0]), "r"(b[1]));
}

__device__ __forceinline__ uint32_t smem_u32(const void* p)
{
    uint32_t a;
    asm("{ .reg .u64 t; cvta.to.shared.u64 t, %1; cvt.u32.u64 %0, t; }" : "=r"(a) : "l"(p));
    return a;
}

__device__ __forceinline__ void ldmx4(uint32_t* r, uint32_t a)
{
    asm volatile("ldmatrix.sync.aligned.m8n8.x4.shared.b16 {%0,%1,%2,%3}, [%4];"
        : "=r"(r[0]), "=r"(r[1]), "=r"(r[2]), "=r"(r[3]) : "r"(a));
}
__device__ __forceinline__ void ldmx4t(uint32_t* r, uint32_t a)
{
    asm volatile("ldmatrix.sync.aligned.m8n8.x4.trans.shared.b16 {%0,%1,%2,%3}, [%4];"
        : "=r"(r[0]), "=r"(r[1]), "=r"(r[2]), "=r"(r[3]) : "r"(a));
}

// ---------------- prep: split + transpose all 6 weights ----------------
__global__ void split_w6_kernel(const float* w0, const float* w1, const float* w2,
                                const float* w3, const float* w4, const float* w5)
{
    __shared__ float tl[32][33];
    int widx = blockIdx.z;
    const float* w = widx==0?w0 : widx==1?w1 : widx==2?w2 : widx==3?w3 : widx==4?w4 : w5;
    int tx = threadIdx.x, ty = threadIdx.y;
    int n0 = blockIdx.x*32, k0 = blockIdx.y*32;
    #pragma unroll
    for (int i = 0; i < 4; i++)
        tl[ty + i*8][tx] = w[(size_t)(k0 + ty + i*8)*Dm + n0 + tx];
    __syncthreads();
    #pragma unroll
    for (int i = 0; i < 4; i++) {
        float v = tl[tx][ty + i*8];
        size_t o = (size_t)(n0 + ty + i*8)*Dm + k0 + tx;
        bsplit(v, g_wth[widx][o], g_wtl[widx][o]);
    }
}

// =========================================================================
// 64x64-tile bf16x3 GEMM, depth-2 pipelined (3-stage smem ring).
// =========================================================================
__global__ void __launch_bounds__(128, 4) mma_gemm64_kernel(
    const __nv_bfloat16* __restrict__ Ah, const __nv_bfloat16* __restrict__ Al,
    const __nv_bfloat16* __restrict__ Bh, const __nv_bfloat16* __restrict__ Bl,
    const float* __restrict__ bias, float* __restrict__ C,
    __nv_bfloat16* __restrict__ Ch, __nv_bfloat16* __restrict__ Cl,
    int N, int K, int gelu)
{
    __shared__ __nv_bfloat16 sAh[3][64*24], sAl[3][64*24];
    __shared__ __nv_bfloat16 sBh[3][64*24], sBl[3][64*24];
    const int tid = threadIdx.x;
    const int lane = tid & 31, warp = tid >> 5;
    const int wm = warp >> 1, wn = warp & 1;
    const int qr = lane >> 2, qc = (lane & 3)*2;
    const int lrow = lane & 15, lkh = (lane >> 4)*8;
    const int row0 = blockIdx.y*64, col0 = blockIdx.x*64;
    const int half = tid >> 6, r = tid & 63;

    const __nv_bfloat16* As = half ? Al : Ah;
    const __nv_bfloat16* Bs = half ? Bl : Bh;
    const int nk = K >> 4;

    {
        const uint4* pa = (const uint4*)(As + (size_t)(row0 + r)*K);
        const uint4* pb = (const uint4*)(Bs + (size_t)(col0 + r)*K);
        uint4 a0 = pa[0], a1 = pa[1], b0 = pb[0], b1 = pb[1];
        __nv_bfloat16* dA = half ? sAl[0] : sAh[0];
        __nv_bfloat16* dB = half ? sBl[0] : sBh[0];
        *(uint4*)&dA[r*24]     = a0; *(uint4*)&dA[r*24 + 8] = a1;
        *(uint4*)&dB[r*24]     = b0; *(uint4*)&dB[r*24 + 8] = b1;
    }
    uint4 Rna0, Rna1, Rnb0, Rnb1;
    if (nk > 1) {
        const uint4* pa = (const uint4*)(As + (size_t)(row0 + r)*K + 16);
        const uint4* pb = (const uint4*)(Bs + (size_t)(col0 + r)*K + 16);
        Rna0 = pa[0]; Rna1 = pa[1]; Rnb0 = pb[0]; Rnb1 = pb[1];
    }
    __syncthreads();

    float acc[2][4][4] = {};
    for (int kc = 0; kc < nk; kc++) {
        if (kc + 1 < nk) {
            const int sb = (kc + 1) % 3;
            __nv_bfloat16* dA = half ? sAl[sb] : sAh[sb];
            __nv_bfloat16* dB = half ? sBl[sb] : sBh[sb];
            *(uint4*)&dA[r*24]     = Rna0; *(uint4*)&dA[r*24 + 8] = Rna1;
            *(uint4*)&dB[r*24]     = Rnb0; *(uint4*)&dB[r*24 + 8] = Rnb1;
        }
        if (kc + 2 < nk) {
            int k0 = (kc + 2)*16;
            const uint4* pa = (const uint4*)(As + (size_t)(row0 + r)*K + k0);
            const uint4* pb = (const uint4*)(Bs + (size_t)(col0 + r)*K + k0);
            Rna0 = pa[0]; Rna1 = pa[1]; Rnb0 = pb[0]; Rnb1 = pb[1];
        }
        __syncthreads();

        const int buf = kc % 3;
        const uint32_t cAh = smem_u32(&sAh[buf][0]);
        const uint32_t cAl = smem_u32(&sAl[buf][0]);
        const uint32_t cBh = smem_u32(&sBh[buf][0]);
        const uint32_t cBl = smem_u32(&sBl[buf][0]);

        uint32_t bh[4][2], bl[4][2];
        #pragma unroll
        for (int ntp = 0; ntp < 2; ntp++) {
            uint32_t off = (uint32_t)(((wn*32 + ntp*16 + lrow)*24 + lkh)*2);
            uint32_t t4[4], u4[4];
            ldmx4(t4, cBh + off);
            ldmx4(u4, cBl + off);
            bh[ntp*2][0]   = t4[0]; bh[ntp*2][1]   = t4[2];
            bh[ntp*2+1][0] = t4[1]; bh[ntp*2+1][1] = t4[3];
            bl[ntp*2][0]   = u4[0]; bl[ntp*2][1]   = u4[2];
            bl[ntp*2+1][0] = u4[1]; bl[ntp*2+1][1] = u4[3];
        }
        #pragma unroll
        for (int mt = 0; mt < 2; mt++) {
            uint32_t offA = (uint32_t)(((wm*32 + mt*16 + lrow)*24 + lkh)*2);
            uint32_t ah[4], al[4];
            ldmx4(ah, cAh + offA);
            ldmx4(al, cAl + offA);
            #pragma unroll
            for (int nt = 0; nt < 4; nt++) {
                mma16816(acc[mt][nt], ah, bh[nt]);
                mma16816(acc[mt][nt], ah, bl[nt]);
                mma16816(acc[mt][nt], al, bh[nt]);
            }
        }
    }

    #pragma unroll
    for (int mt = 0; mt < 2; mt++) {
        int gr = row0 + wm*32 + mt*16 + qr;
        #pragma unroll
        for (int nt = 0; nt < 4; nt++) {
            int gc = col0 + wn*32 + nt*8 + qc;
            float v0 = acc[mt][nt][0] + bias[gc];
            float v1 = acc[mt][nt][1] + bias[gc+1];
            float v2 = acc[mt][nt][2] + bias[gc];
            float v3 = acc[mt][nt][3] + bias[gc+1];
            if (gelu) {
                v0 = 0.5f*v0*(1.0f + erff(v0*0.70710678118654752f));
                v1 = 0.5f*v1*(1.0f + erff(v1*0.70710678118654752f));
                v2 = 0.5f*v2*(1.0f + erff(v2*0.70710678118654752f));
                v3 = 0.5f*v3*(1.0f + erff(v3*0.70710678118654752f));
            }
            if (C) {
                *(float2*)&C[(size_t)gr*N + gc]     = make_float2(v0, v1);
                *(float2*)&C[(size_t)(gr+8)*N + gc] = make_float2(v2, v3);
            }
            if (Ch) {
                uint32_t h01, l01, h23, l23;
                split2(v0, v1, h01, l01);
                split2(v2, v3, h23, l23);
                *(uint32_t*)&Ch[(size_t)gr*N + gc]     = h01;
                *(uint32_t*)&Cl[(size_t)gr*N + gc]     = l01;
                *(uint32_t*)&Ch[(size_t)(gr+8)*N + gc] = h23;
                *(uint32_t*)&Cl[(size_t)(gr+8)*N + gc] = l23;
            }
        }
    }
}

// =========================================================================
// 64x32-tile bf16x3 GEMM, depth-2 pipelined (3-stage smem ring). MLP GEMMs.
// =========================================================================
__global__ void __launch_bounds__(128, 4) mma_gemm64x32_kernel(
    const __nv_bfloat16* __restrict__ Ah, const __nv_bfloat16* __restrict__ Al,
    const __nv_bfloat16* __restrict__ Bh, const __nv_bfloat16* __restrict__ Bl,
    const float* __restrict__ bias, float* __restrict__ C,
    __nv_bfloat16* __restrict__ Ch, __nv_bfloat16* __restrict__ Cl,
    int N, int K, int gelu)
{
    __shared__ __nv_bfloat16 sAh[3][64*24], sAl[3][64*24];
    __shared__ __nv_bfloat16 sBh[3][32*24], sBl[3][32*24];
    const int tid = threadIdx.x;
    const int lane = tid & 31, warp = tid >> 5;
    const int wm = warp >> 1, wn = warp & 1;
    const int qr = lane >> 2, qc = (lane & 3)*2;
    const int lrow = lane & 15, lkh = (lane >> 4)*8;
    const int row0 = blockIdx.y*64, col0 = blockIdx.x*32;
    const int half = tid >> 6, r = tid & 63;

    const __nv_bfloat16* As = half ? Al : Ah;
    const __nv_bfloat16* Bs = half ? Bl : Bh;
    const int nk = K >> 4;

    {
        const uint4* pa = (const uint4*)(As + (size_t)(row0 + r)*K);
        uint4 a0 = pa[0], a1 = pa[1];
        __nv_bfloat16* dA = half ? sAl[0] : sAh[0];
        *(uint4*)&dA[r*24]     = a0; *(uint4*)&dA[r*24 + 8] = a1;
        if (r < 32) {
            const uint4* pb = (const uint4*)(Bs + (size_t)(col0 + r)*K);
            uint4 b0 = pb[0], b1 = pb[1];
            __nv_bfloat16* dB = half ? sBl[0] : sBh[0];
            *(uint4*)&dB[r*24]     = b0; *(uint4*)&dB[r*24 + 8] = b1;
        }
    }
    uint4 Rna0, Rna1, Rnb0, Rnb1;
    if (nk > 1) {
        const uint4* pa = (const uint4*)(As + (size_t)(row0 + r)*K + 16);
        Rna0 = pa[0]; Rna1 = pa[1];
        if (r < 32) {
            const uint4* pb = (const uint4*)(Bs + (size_t)(col0 + r)*K + 16);
            Rnb0 = pb[0]; Rnb1 = pb[1];
        }
    }
    __syncthreads();

    float acc[2][2][4] = {};
    for (int kc = 0; kc < nk; kc++) {
        if (kc + 1 < nk) {
            const int sb = (kc + 1) % 3;
            __nv_bfloat16* dA = half ? sAl[sb] : sAh[sb];
            *(uint4*)&dA[r*24]     = Rna0; *(uint4*)&dA[r*24 + 8] = Rna1;
            if (r < 32) {
                __nv_bfloat16* dB = half ? sBl[sb] : sBh[sb];
                *(uint4*)&dB[r*24]     = Rnb0; *(uint4*)&dB[r*24 + 8] = Rnb1;
            }
        }
        if (kc + 2 < nk) {
            int k0 = (kc + 2)*16;
            const uint4* pa = (const uint4*)(As + (size_t)(row0 + r)*K + k0);
            Rna0 = pa[0]; Rna1 = pa[1];
            if (r < 32) {
                const uint4* pb = (const uint4*)(Bs + (size_t)(col0 + r)*K + k0);
                Rnb0 = pb[0]; Rnb1 = pb[1];
            }
        }
        __syncthreads();

        const int buf = kc % 3;
        const uint32_t cAh = smem_u32(&sAh[buf][0]);
        const uint32_t cAl = smem_u32(&sAl[buf][0]);
        const uint32_t cBh = smem_u32(&sBh[buf][0]);
        const uint32_t cBl = smem_u32(&sBl[buf][0]);

        uint32_t bh[2][2], bl[2][2];
        {
            uint32_t off = (uint32_t)(((wn*16 + lrow)*24 + lkh)*2);
            uint32_t t4[4], u4[4];
            ldmx4(t4, cBh + off);
            ldmx4(u4, cBl + off);
            bh[0][0] = t4[0]; bh[0][1] = t4[2];
            bh[1][0] = t4[1]; bh[1][1] = t4[3];
            bl[0][0] = u4[0]; bl[0][1] = u4[2];
            bl[1][0] = u4[1]; bl[1][1] = u4[3];
        }
        #pragma unroll
        for (int mt = 0; mt < 2; mt++) {
            uint32_t offA = (uint32_t)(((wm*32 + mt*16 + lrow)*24 + lkh)*2);
            uint32_t ah[4], al[4];
            ldmx4(ah, cAh + offA);
            ldmx4(al, cAl + offA);
            #pragma unroll
            for (int nt = 0; nt < 2; nt++) {
                mma16816(acc[mt][nt], ah, bh[nt]);
                mma16816(acc[mt][nt], ah, bl[nt]);
                mma16816(acc[mt][nt], al, bh[nt]);
            }
        }
    }

    #pragma unroll
    for (int mt = 0; mt < 2; mt++) {
        int gr = row0 + wm*32 + mt*16 + qr;
        #pragma unroll
        for (int nt = 0; nt < 2; nt++) {
            int gc = col0 + wn*16 + nt*8 + qc;
            float v0 = acc[mt][nt][0] + bias[gc];
            float v1 = acc[mt][nt][1] + bias[gc+1];
            float v2 = acc[mt][nt][2] + bias[gc];
            float v3 = acc[mt][nt][3] + bias[gc+1];
            if (gelu) {
                v0 = 0.5f*v0*(1.0f + erff(v0*0.70710678118654752f));
                v1 = 0.5f*v1*(1.0f + erff(v1*0.70710678118654752f));
                v2 = 0.5f*v2*(1.0f + erff(v2*0.70710678118654752f));
                v3 = 0.5f*v3*(1.0f + erff(v3*0.70710678118654752f));
            }
            if (C) {
                *(float2*)&C[(size_t)gr*N + gc]     = make_float2(v0, v1);
                *(float2*)&C[(size_t)(gr+8)*N + gc] = make_float2(v2, v3);
            }
            if (Ch) {
                uint32_t h01, l01, h23, l23;
                split2(v0, v1, h01, l01);
                split2(v2, v3, h23, l23);
                *(uint32_t*)&Ch[(size_t)gr*N + gc]     = h01;
                *(uint32_t*)&Cl[(size_t)gr*N + gc]     = l01;
                *(uint32_t*)&Ch[(size_t)(gr+8)*N + gc] = h23;
                *(uint32_t*)&Cl[(size_t)(gr+8)*N + gc] = l23;
            }
        }
    }
}

// =========================================================================
// bf16x3 GEMM with fused fp32->hi/lo A conversion (projections), 128x128.
// =========================================================================
__device__ __forceinline__ void mma_gemm_f32A_body(
    const float* __restrict__ Afp,
    const __nv_bfloat16* __restrict__ Bh, const __nv_bfloat16* __restrict__ Bl,
    const float* __restrict__ bias, float* __restrict__ C,
    __nv_bfloat16* __restrict__ Ch, __nv_bfloat16* __restrict__ Cl,
    int N, int K)
{
    __shared__ __nv_bfloat16 sAh[2][128*24], sAl[2][128*24];
    __shared__ __nv_bfloat16 sBh[2][128*24], sBl[2][128*24];
    const int tid = threadIdx.x;
    const int lane = tid & 31, warp = tid >> 5;
    const int wm = warp >> 2, wn = warp & 3;
    const int qr = lane >> 2, qc = (lane & 3)*2;
    const int lrow = lane & 15, lkh = (lane >> 4)*8;
    const int row0 = blockIdx.y*128, col0 = blockIdx.x*128;
    const int half = tid >> 7, r = tid & 127;

    if (half == 0) {
        const float4* pa = (const float4*)(Afp + (size_t)(row0 + r)*K);
        float4 f0 = pa[0], f1 = pa[1], f2 = pa[2], f3 = pa[3];
        float fv[16] = {f0.x,f0.y,f0.z,f0.w, f1.x,f1.y,f1.z,f1.w,
                        f2.x,f2.y,f2.z,f2.w, f3.x,f3.y,f3.z,f3.w};
        #pragma unroll
        for (int c2 = 0; c2 < 8; c2++) {
            uint32_t h2, l2;
            split2(fv[c2*2], fv[c2*2+1], h2, l2);
            *(uint32_t*)&sAh[0][r*24 + c2*2] = h2;
            *(uint32_t*)&sAl[0][r*24 + c2*2] = l2;
        }
    } else {
        const uint4* pbh = (const uint4*)(Bh + (size_t)(col0 + r)*K);
        const uint4* pbl = (const uint4*)(Bl + (size_t)(col0 + r)*K);
        uint4 b0 = pbh[0], b1 = pbh[1], c0 = pbl[0], c1 = pbl[1];
        *(uint4*)&sBh[0][r*24]     = b0; *(uint4*)&sBh[0][r*24 + 8] = b1;
        *(uint4*)&sBl[0][r*24]     = c0; *(uint4*)&sBl[0][r*24 + 8] = c1;
    }
    __syncthreads();

    float acc[4][4][4] = {};
    const int nk = K >> 4;
    for (int kc = 0; kc < nk; kc++) {
        const int buf = kc & 1;
        float nfv[16];
        uint4 nb0, nb1, nc0, nc1;
        if (kc + 1 < nk) {
            int k0 = (kc + 1)*16;
            if (half == 0) {
                const float4* pa = (const float4*)(Afp + (size_t)(row0 + r)*K + k0);
                float4 f0 = pa[0], f1 = pa[1], f2 = pa[2], f3 = pa[3];
                nfv[0]=f0.x; nfv[1]=f0.y; nfv[2]=f0.z; nfv[3]=f0.w;
                nfv[4]=f1.x; nfv[5]=f1.y; nfv[6]=f1.z; nfv[7]=f1.w;
                nfv[8]=f2.x; nfv[9]=f2.y; nfv[10]=f2.z; nfv[11]=f2.w;
                nfv[12]=f3.x; nfv[13]=f3.y; nfv[14]=f3.z; nfv[15]=f3.w;
            } else {
                const uint4* pbh = (const uint4*)(Bh + (size_t)(col0 + r)*K + k0);
                const uint4* pbl = (const uint4*)(Bl + (size_t)(col0 + r)*K + k0);
                nb0 = pbh[0]; nb1 = pbh[1]; nc0 = pbl[0]; nc1 = pbl[1];
            }
        }

        const uint32_t cAh = smem_u32(&sAh[buf][0]);
        const uint32_t cAl = smem_u32(&sAl[buf][0]);
        const uint32_t cBh = smem_u32(&sBh[buf][0]);
        const uint32_t cBl = smem_u32(&sBl[buf][0]);

        uint32_t bh[4][2], bl[4][2];
        #pragma unroll
        for (int ntp = 0; ntp < 2; ntp++) {
            uint32_t off = (uint32_t)(((wn*32 + ntp*16 + lrow)*24 + lkh)*2);
            uint32_t t4[4], u4[4];
            ldmx4(t4, cBh + off);
            ldmx4(u4, cBl + off);
            bh[ntp*2][0]   = t4[0]; bh[ntp*2][1]   = t4[2];
            bh[ntp*2+1][0] = t4[1]; bh[ntp*2+1][1] = t4[3];
            bl[ntp*2][0]   = u4[0]; bl[ntp*2][1]   = u4[2];
            bl[ntp*2+1][0] = u4[1]; bl[ntp*2+1][1] = u4[3];
        }
        #pragma unroll
        for (int mt = 0; mt < 4; mt++) {
            uint32_t offA = (uint32_t)(((wm*64 + mt*16 + lrow)*24 + lkh)*2);
            uint32_t ah[4], al[4];
            ldmx4(ah, cAh + offA);
            ldmx4(al, cAl + offA);
            #pragma unroll
            for (int nt = 0; nt < 4; nt++) {
                mma16816(acc[mt][nt], ah, bh[nt]);
                mma16816(acc[mt][nt], ah, bl[nt]);
                mma16816(acc[mt][nt], al, bh[nt]);
            }
        }

        if (kc + 1 < nk) {
            const int nb = buf ^ 1;
            if (half == 0) {
                #pragma unroll
                for (int c2 = 0; c2 < 8; c2++) {
                    uint32_t h2, l2;
                    split2(nfv[c2*2], nfv[c2*2+1], h2, l2);
                    *(uint32_t*)&sAh[nb][r*24 + c2*2] = h2;
                    *(uint32_t*)&sAl[nb][r*24 + c2*2] = l2;
                }
            } else {
                *(uint4*)&sBh[nb][r*24]     = nb0; *(uint4*)&sBh[nb][r*24 + 8] = nb1;
                *(uint4*)&sBl[nb][r*24]     = nc0; *(uint4*)&sBl[nb][r*24 + 8] = nc1;
            }
        }
        __syncthreads();
    }

    #pragma unroll
    for (int mt = 0; mt < 4; mt++) {
        int gr = row0 + wm*64 + mt*16 + qr;
        #pragma unroll
        for (int nt = 0; nt < 4; nt++) {
            int gc = col0 + wn*32 + nt*8 + qc;
            float v0 = acc[mt][nt][0] + bias[gc];
            float v1 = acc[mt][nt][1] + bias[gc+1];
            float v2 = acc[mt][nt][2] + bias[gc];
            float v3 = acc[mt][nt][3] + bias[gc+1];
            if (C) {
                *(float2*)&C[(size_t)gr*N + gc]     = make_float2(v0, v1);
                *(float2*)&C[(size_t)(gr+8)*N + gc] = make_float2(v2, v3);
            }
            if (Ch) {
                uint32_t h01, l01, h23, l23;
                split2(v0, v1, h01, l01);
                split2(v2, v3, h23, l23);
                *(uint32_t*)&Ch[(size_t)gr*N + gc]     = h01;
                *(uint32_t*)&Cl[(size_t)gr*N + gc]     = l01;
                *(uint32_t*)&Ch[(size_t)(gr+8)*N + gc] = h23;
                *(uint32_t*)&Cl[(size_t)(gr+8)*N + gc] = l23;
            }
        }
    }
}

__global__ void __launch_bounds__(256, 2) proj3_mma_kernel(
    const float* q_in, const float* k_in, const float* v_in,
    const float* bq, const float* bk, const float* bv)
{
    int z = blockIdx.z;
    if (z == 0)
        mma_gemm_f32A_body(q_in, g_wth[0], g_wtl[0], bq, g_q, g_qh, g_ql, Dm, Dm);
    else if (z == 1)
        mma_gemm_f32A_body(k_in, g_wth[1], g_wtl[1], bk, g_k, g_kh, g_kl, Dm, Dm);
    else
        mma_gemm_f32A_body(v_in, g_wth[2], g_wtl[2], bv, g_v, g_vh, g_vl, Dm, Dm);
}

// =========================================================================
// dense QK^T (bf16x3 mma) + fused row stats, ldmatrix fragments
// =========================================================================
extern __shared__ __nv_bfloat16 scsm[];
__global__ void __launch_bounds__(256, 2) scores_stats_mma_kernel(float scale)
{
    __nv_bfloat16* sAh = scsm;
    __nv_bfloat16* sAl = scsm + 128*72;
    __nv_bfloat16* sBh = scsm + 2*128*72;
    __nv_bfloat16* sBl = scsm + 3*128*72;
    __shared__ float s4a[128][4], s4b[128][4], srm[128];

    const int tid = threadIdx.x;
    const int lane = tid & 31, warp = tid >> 5;
    const int wm = warp >> 2, wn = warp & 3;
    const int qr = lane >> 2;
    const int bh = blockIdx.z;
    const int b = bh >> 3, h = bh & 7;
    const int i0 = blockIdx.y*128, j0 = blockIdx.x*128;

    const __nv_bfloat16* Qhp = g_qh + ((size_t)(b*Ls) + i0)*Dm + h*HDim;
    const __nv_bfloat16* Qlp = g_ql + ((size_t)(b*Ls) + i0)*Dm + h*HDim;
    const __nv_bfloat16* Khp = g_kh + ((size_t)(b*Ls) + j0)*Dm + h*HDim;
    const __nv_bfloat16* Klp = g_kl + ((size_t)(b*Ls) + j0)*Dm + h*HDim;

    #pragma unroll
    for (int i = 0; i < 4; i++) {
        int slot = tid*4 + i;
        int row = slot >> 3, c = slot & 7;
        *(uint4*)&sAh[row*72 + c*8] = *(const uint4*)&Qhp[(size_t)row*Dm + c*8];
        *(uint4*)&sAl[row*72 + c*8] = *(const uint4*)&Qlp[(size_t)row*Dm + c*8];
        *(uint4*)&sBh[row*72 + c*8] = *(const uint4*)&Khp[(size_t)row*Dm + c*8];
        *(uint4*)&sBl[row*72 + c*8] = *(const uint4*)&Klp[(size_t)row*Dm + c*8];
    }
    __syncthreads();

    const uint32_t sc0 = smem_u32(scsm);
    const uint32_t aAh = sc0, aAl = sc0 + 128*72*2, aBh = sc0 + 2*128*72*2, aBl = sc0 + 3*128*72*2;
    const int lrow = lane & 15, lkh = (lane >> 4)*8;

    float acc[4][4][4] = {};
    #pragma unroll
    for (int kc = 0; kc < 4; kc++) {
        const int ko = kc*16;
        uint32_t Bh4[2][4], Bl4[2][4];
        #pragma unroll
        for (int ntp = 0; ntp < 2; ntp++) {
            uint32_t off = ((wn*32 + ntp*16 + lrow)*72 + ko + lkh)*2;
            ldmx4(Bh4[ntp], aBh + off);
            ldmx4(Bl4[ntp], aBl + off);
        }
        #pragma unroll
        for (int mt = 0; mt < 4; mt++) {
            uint32_t offA = ((wm*64 + mt*16 + lrow)*72 + ko + lkh)*2;
            uint32_t ah[4], al[4];
            ldmx4(ah, aAh + offA);
            ldmx4(al, aAl + offA);
            #pragma unroll
            for (int nt = 0; nt < 4; nt++) {
                uint32_t bhf[2] = { Bh4[nt>>1][nt&1], Bh4[nt>>1][(nt&1)+2] };
                uint32_t blf[2] = { Bl4[nt>>1][nt&1], Bl4[nt>>1][(nt&1)+2] };
                mma16816(acc[mt][nt], ah, bhf);
                mma16816(acc[mt][nt], ah, blf);
                mma16816(acc[mt][nt], al, bhf);
            }
        }
    }

    #pragma unroll
    for (int mt = 0; mt < 4; mt++) {
        float m0 = -INFINITY, m1 = -INFINITY;
        #pragma unroll
        for (int nt = 0; nt < 4; nt++) {
            m0 = fmaxf(m0, fmaxf(acc[mt][nt][0], acc[mt][nt][1]));
            m1 = fmaxf(m1, fmaxf(acc[mt][nt][2], acc[mt][nt][3]));
        }
        m0 = fmaxf(m0, __shfl_xor_sync(0xFFFFFFFFu, m0, 1));
        m0 = fmaxf(m0, __shfl_xor_sync(0xFFFFFFFFu, m0, 2));
        m1 = fmaxf(m1, __shfl_xor_sync(0xFFFFFFFFu, m1, 1));
        m1 = fmaxf(m1, __shfl_xor_sync(0xFFFFFFFFu, m1, 2));
        if ((lane & 3) == 0) {
            s4a[wm*64 + mt*16 + qr][wn]     = m0;
            s4a[wm*64 + mt*16 + 8 + qr][wn] = m1;
        }
    }
    __syncthreads();
    if (tid < 128)
        srm[tid] = fmaxf(fmaxf(s4a[tid][0], s4a[tid][1]), fmaxf(s4a[tid][2], s4a[tid][3]));
    __syncthreads();

    #pragma unroll
    for (int mt = 0; mt < 4; mt++) {
        int lr0 = wm*64 + mt*16 + qr, lr1 = lr0 + 8;
        float rm0 = srm[lr0]*scale, rm1 = srm[lr1]*scale;
        float se0 = 0.f, se1 = 0.f, ss0 = 0.f, ss1 = 0.f;
        #pragma unroll
        for (int nt = 0; nt < 4; nt++) {
            float x0 = acc[mt][nt][0]*scale, x1 = acc[mt][nt][1]*scale;
            float x2 = acc[mt][nt][2]*scale, x3 = acc[mt][nt][3]*scale;
            se0 += __expf(x0 - rm0) + __expf(x1 - rm0);
            se1 += __expf(x2 - rm1) + __expf(x3 - rm1);
            ss0 += x0 + x1; ss1 += x2 + x3;
        }
        se0 += __shfl_xor_sync(0xFFFFFFFFu, se0, 1); se0 += __shfl_xor_sync(0xFFFFFFFFu, se0, 2);
        se1 += __shfl_xor_sync(0xFFFFFFFFu, se1, 1); se1 += __shfl_xor_sync(0xFFFFFFFFu, se1, 2);
        ss0 += __shfl_xor_sync(0xFFFFFFFFu, ss0, 1); ss0 += __shfl_xor_sync(0xFFFFFFFFu, ss0, 2);
        ss1 += __shfl_xor_sync(0xFFFFFFFFu, ss1, 1); ss1 += __shfl_xor_sync(0xFFFFFFFFu, ss1, 2);
        if ((lane & 3) == 0) {
            s4b[lr0][wn] = se0; s4b[lr1][wn] = se1;
            s4a[lr0][wn] = ss0; s4a[lr1][wn] = ss1;
        }
    }
    __syncthreads();
    if (tid < 128) {
        int rowg = bh*Ls + i0 + tid;
        int jt = blockIdx.x;
        g_pmax[(size_t)rowg*NJT + jt] = srm[tid]*scale;
        g_pse [(size_t)rowg*NJT + jt] = s4b[tid][0]+s4b[tid][1]+s4b[tid][2]+s4b[tid][3];
        g_psum[(size_t)rowg*NJT + jt] = s4a[tid][0]+s4a[tid][1]+s4a[tid][2]+s4a[tid][3];
    }
}

// ---------------- compress: mean of 4 rows -> splits ----------------
__global__ void compress_kernel()
{
    int e4 = blockIdx.x*blockDim.x + threadIdx.x;
    int b = e4 / (LcC*Dm/4);
    int r = e4 % (LcC*Dm/4);
    int m = r / (Dm/4), d4 = r % (Dm/4);
    const float4* k4 = (const float4*)g_k;
    const float4* v4 = (const float4*)g_v;
    size_t base = ((size_t)(b*Ls + m*4)*Dm)/4 + d4;
    float4 a = k4[base], bb = k4[base+128], c = k4[base+256], d = k4[base+384];
    float ox = 0.25f*(a.x+bb.x+c.x+d.x), oy = 0.25f*(a.y+bb.y+c.y+d.y);
    float oz = 0.25f*(a.z+bb.z+c.z+d.z), ow = 0.25f*(a.w+bb.w+c.w+d.w);
    bsplit(ox, g_kcpreh[e4*4+0], g_kcprel[e4*4+0]);
    bsplit(oy, g_kcpreh[e4*4+1], g_kcprel[e4*4+1]);
    bsplit(oz, g_kcpreh[e4*4+2], g_kcprel[e4*4+2]);
    bsplit(ow, g_kcpreh[e4*4+3], g_kcprel[e4*4+3]);
    a = v4[base]; bb = v4[base+128]; c = v4[base+256]; d = v4[base+384];
    ox = 0.25f*(a.x+bb.x+c.x+d.x); oy = 0.25f*(a.y+bb.y+c.y+d.y);
    oz = 0.25f*(a.z+bb.z+c.z+d.z); ow = 0.25f*(a.w+bb.w+c.w+d.w);
    bsplit(ox, g_vch[e4*4+0], g_vcl[e4*4+0]);
    bsplit(oy, g_vch[e4*4+1], g_vcl[e4*4+1]);
    bsplit(oz, g_vch[e4*4+2], g_vcl[e4*4+2]);
    bsplit(ow, g_vch[e4*4+3], g_vcl[e4*4+3]);
}

// ---------------- importance merge ----------------
__global__ void impfinal_kernel()
{
    int warp = (blockIdx.x*blockDim.x + threadIdx.x) >> 5;
    int lane = threadIdx.x & 31;
    float pm = -INFINITY, pe = 0.f, ps = 0.f;
    if (lane < NJT) {
        pm = g_pmax[(size_t)warp*NJT + lane];
        pe = g_pse [(size_t)warp*NJT + lane];
        ps = g_psum[(size_t)warp*NJT + lane];
    }
    float m = pm;
    #pragma unroll
    for (int o = 8; o; o >>= 1) m = fmaxf(m, __shfl_xor_sync(0xFFFFFFFFu, m, o));
    float se = (lane < NJT) ? pe * __expf(pm - m) : 0.f;
    #pragma unroll
    for (int o = 8; o; o >>= 1) {
        se += __shfl_xor_sync(0xFFFFFFFFu, se, o);
        ps += __shfl_xor_sync(0xFFFFFFFFu, ps, o);
    }
    if (lane == 0)
        g_imp[warp] = m + logf(se) - 7.6246189861593985f - ps * (1.0f/2048.0f);
}

// ---------------- top-8 ----------------
__global__ void topk_kernel()
{
    int bh = blockIdx.x;
    const float* imp = g_imp + bh*Ls;
    __shared__ float bv[256];
    __shared__ int   bi[256];
    __shared__ int   chosen[NSEL];
    int t = threadIdx.x;
    for (int itu = 0; itu < NSEL; itu++) {
        float best = -INFINITY; int bidx = 0x7FFFFFFF;
        for (int j = t; j < Ls; j += 256) {
            bool skip = false;
            for (int c = 0; c < itu; c++) if (chosen[c] == j) skip = true;
            if (skip) continue;
            float vv = imp[j];
            if (vv > best || (vv == best && j < bidx)) { best = vv; bidx = j; }
        }
        bv[t] = best; bi[t] = bidx;
        __syncthreads();
        for (int s2 = 128; s2; s2 >>= 1) {
            if (t < s2) {
                if (bv[t+s2] > bv[t] || (bv[t+s2] == bv[t] && bi[t+s2] < bi[t])) {
                    bv[t] = bv[t+s2]; bi[t] = bi[t+s2];
                }
            }
            __syncthreads();
        }
        if (t == 0) { chosen[itu] = bi[0]; g_selidx[bh*NSEL + itu] = bi[0]; }
        __syncthreads();
    }
}

// =========================================================================
// fused flash attention, 128-row Q tiles, 8 warps all in M, band chunk skip.
// =========================================================================
extern __shared__ char fsm2[];
__global__ void __launch_bounds__(256, 2) flash_mma_kernel(
    const __nv_bfloat16* __restrict__ Qh, const __nv_bfloat16* __restrict__ Ql,
    const __nv_bfloat16* __restrict__ Khg, const __nv_bfloat16* __restrict__ Klg,
    const __nv_bfloat16* __restrict__ Vhg, const __nv_bfloat16* __restrict__ Vlg,
    const __nv_bfloat16* __restrict__ Khc, const __nv_bfloat16* __restrict__ Klc,
    const __nv_bfloat16* __restrict__ Vhc, const __nv_bfloat16* __restrict__ Vlc,
    float* __restrict__ OutL, float* __restrict__ OutG)
{
    __nv_bfloat16* sQh = (__nv_bfloat16*)fsm2;   // [128][72]
    __nv_bfloat16* sQl = sQh + 128*72;
    __nv_bfloat16* sKh = sQl + 128*72;           // [64][72]
    __nv_bfloat16* sKl = sKh + 64*72;
    __nv_bfloat16* sVh = sKl + 64*72;            // natural [j][d]
    __nv_bfloat16* sVl = sVh + 64*72;

    const int z = blockIdx.z;
    const __nv_bfloat16* Kh = z ? Khc : Khg;
    const __nv_bfloat16* Kl = z ? Klc : Klg;
    const __nv_bfloat16* Vh = z ? Vhc : Vhg;
    const __nv_bfloat16* Vl = z ? Vlc : Vlg;
    float* Out = z ? OutG : OutL;
    const int LK = z ? LcC : Ls;
    const int nchunks = z ? 8 : 4;
    const int local = z ? 0 : 1;

    const int tid = threadIdx.x;
    const int lane = tid & 31, w = tid >> 5;
    const int qr = lane >> 2, qc = (lane & 3)*2;
    const int lrow = lane & 15, lkh = (lane >> 4)*8;
    const int bh = blockIdx.y;
    const int b = bh >> 3, h = bh & 7;
    const int i0 = blockIdx.x*128;
    const size_t hoff = (size_t)h*HDim;

    const uint32_t sb = smem_u32(fsm2);
    const uint32_t aQh = sb, aQl = sb + 18432;
    const uint32_t aKh = sb + 36864, aKl = sb + 46080;
    const uint32_t aVh = sb + 55296, aVl = sb + 64512;

    {
        int row = tid >> 1, part = (tid & 1)*32;
        const uint4* ph = (const uint4*)(Qh + ((size_t)(b*Ls) + i0 + row)*Dm + hoff + part);
        const uint4* pl = (const uint4*)(Ql + ((size_t)(b*Ls) + i0 + row)*Dm + hoff + part);
        #pragma unroll
        for (int j = 0; j < 4; j++) {
            *(uint4*)&sQh[row*72 + part + j*8] = ph[j];
            *(uint4*)&sQl[row*72 + part + j*8] = pl[j];
        }
    }

    float accO[8][4] = {};
    float mr0 = -INFINITY, mr1 = -INFINITY;
    float lr0 = 0.f, lr1 = 0.f;
    const int ir0 = i0 + w*16 + qr, ir1 = ir0 + 8;

    for (int c = 0; c < nchunks; c++) {
        int jbase = (local ? i0 - 64 : 0) + c*64;
        __syncthreads();
        {
            int row = tid >> 2, c16 = (tid & 3)*16;
            int jg = jbase + row;
            uint4 kh0 = {0,0,0,0}, kh1 = {0,0,0,0}, kl0 = {0,0,0,0}, kl1 = {0,0,0,0};
            uint4 vh0 = {0,0,0,0}, vh1 = {0,0,0,0}, vl0 = {0,0,0,0}, vl1 = {0,0,0,0};
            if (jg >= 0 && jg < LK) {
                const uint4* ph = (const uint4*)(Kh + ((size_t)(b*LK) + jg)*Dm + hoff + c16);
                const uint4* pl = (const uint4*)(Kl + ((size_t)(b*LK) + jg)*Dm + hoff + c16);
                kh0 = ph[0]; kh1 = ph[1]; kl0 = pl[0]; kl1 = pl[1];
                ph = (const uint4*)(Vh + ((size_t)(b*LK) + jg)*Dm + hoff + c16);
                pl = (const uint4*)(Vl + ((size_t)(b*LK) + jg)*Dm + hoff + c16);
                vh0 = ph[0]; vh1 = ph[1]; vl0 = pl[0]; vl1 = pl[1];
            }
            *(uint4*)&sKh[row*72 + c16] = kh0; *(uint4*)&sKh[row*72 + c16 + 8] = kh1;
            *(uint4*)&sKl[row*72 + c16] = kl0; *(uint4*)&sKl[row*72 + c16 + 8] = kl1;
            *(uint4*)&sVh[row*72 + c16] = vh0; *(uint4*)&sVh[row*72 + c16 + 8] = vh1;
            *(uint4*)&sVl[row*72 + c16] = vl0; *(uint4*)&sVl[row*72 + c16 + 8] = vl1;
        }
        __syncthreads();

        if (local) {
            int c64 = c*64;
            if (c64 < w*16 - 63 || c64 > w*16 + 143) continue;
        }

        float s[8][4] = {};
        #pragma unroll
        for (int kc = 0; kc < 4; kc++) {
            int ko = kc*16;
            uint32_t offA = ((w*16 + lrow)*72 + ko + lkh)*2;
            uint32_t ah[4], al[4];
            ldmx4(ah, aQh + offA);
            ldmx4(al, aQl + offA);
            #pragma unroll
            for (int ntp = 0; ntp < 4; ntp++) {
                uint32_t offB = ((ntp*16 + lrow)*72 + ko + lkh)*2;
                uint32_t kh4[4], kl4[4];
                ldmx4(kh4, aKh + offB);
                ldmx4(kl4, aKl + offB);
                uint32_t bhf0[2] = { kh4[0], kh4[2] }, bhf1[2] = { kh4[1], kh4[3] };
                uint32_t blf0[2] = { kl4[0], kl4[2] }, blf1[2] = { kl4[1], kl4[3] };
                mma16816(s[ntp*2],   ah, bhf0);
                mma16816(s[ntp*2],   ah, blf0);
                mma16816(s[ntp*2],   al, bhf0);
                mma16816(s[ntp*2+1], ah, bhf1);
                mma16816(s[ntp*2+1], ah, blf1);
                mma16816(s[ntp*2+1], al, bhf1);
            }
        }

        float m0 = -INFINITY, m1 = -INFINITY;
        #pragma unroll
        for (int nt = 0; nt < 8; nt++) {
            int jc0 = jbase + nt*8 + qc;
            int jc1 = jc0 + 1;
            #pragma unroll
            for (int rg = 0; rg < 4; rg++) s[nt][rg] *= 0.125f;
            bool ok00 = true, ok01 = true, ok10 = true, ok11 = true;
            if (local) {
                ok00 = (jc0 >= 0) & (jc0 < LK) & (jc0 >= ir0-64) & (jc0 <= ir0+64);
                ok01 = (jc1 >= 0) & (jc1 < LK) & (jc1 >= ir0-64) & (jc1 <= ir0+64);
                ok10 = (jc0 >= 0) & (jc0 < LK) & (jc0 >= ir1-64) & (jc0 <= ir1+64);
                ok11 = (jc1 >= 0) & (jc1 < LK) & (jc1 >= ir1-64) & (jc1 <= ir1+64);
            }
            if (ok00) m0 = fmaxf(m0, s[nt][0]);
            if (ok01) m0 = fmaxf(m0, s[nt][1]);
            if (ok10) m1 = fmaxf(m1, s[nt][2]);
            if (ok11) m1 = fmaxf(m1, s[nt][3]);
        }
        m0 = fmaxf(m0, __shfl_xor_sync(0xFFFFFFFFu, m0, 1));
        m0 = fmaxf(m0, __shfl_xor_sync(0xFFFFFFFFu, m0, 2));
        m1 = fmaxf(m1, __shfl_xor_sync(0xFFFFFFFFu, m1, 1));
        m1 = fmaxf(m1, __shfl_xor_sync(0xFFFFFFFFu, m1, 2));
        float mn0 = fmaxf(mr0, m0), mn1 = fmaxf(mr1, m1);
        float cf0 = (mn0 == -INFINITY) ? 1.f : __expf(mr0 - mn0);
        float cf1 = (mn1 == -INFINITY) ? 1.f : __expf(mr1 - mn1);
        mr0 = mn0; mr1 = mn1;

        float ps0 = 0.f, ps1 = 0.f;
        #pragma unroll
        for (int nt = 0; nt < 8; nt++) {
            int jc0 = jbase + nt*8 + qc;
            int jc1 = jc0 + 1;
            bool ok00 = true, ok01 = true, ok10 = true, ok11 = true;
            if (local) {
                ok00 = (jc0 >= 0) & (jc0 < LK) & (jc0 >= ir0-64) & (jc0 <= ir0+64);
                ok01 = (jc1 >= 0) & (jc1 < LK) & (jc1 >= ir0-64) & (jc1 <= ir0+64);
                ok10 = (jc0 >= 0) & (jc0 < LK) & (jc0 >= ir1-64) & (jc0 <= ir1+64);
                ok11 = (jc1 >= 0) & (jc1 < LK) & (jc1 >= ir1-64) & (jc1 <= ir1+64);
            }
            s[nt][0] = ok00 ? __expf(s[nt][0] - mn0) : 0.f;
            s[nt][1] = ok01 ? __expf(s[nt][1] - mn0) : 0.f;
            s[nt][2] = ok10 ? __expf(s[nt][2] - mn1) : 0.f;
            s[nt][3] = ok11 ? __expf(s[nt][3] - mn1) : 0.f;
            ps0 += s[nt][0] + s[nt][1];
            ps1 += s[nt][2] + s[nt][3];
        }
        ps0 += __shfl_xor_sync(0xFFFFFFFFu, ps0, 1); ps0 += __shfl_xor_sync(0xFFFFFFFFu, ps0, 2);
        ps1 += __shfl_xor_sync(0xFFFFFFFFu, ps1, 1); ps1 += __shfl_xor_sync(0xFFFFFFFFu, ps1, 2);
        lr0 = lr0*cf0 + ps0;
        lr1 = lr1*cf1 + ps1;

        #pragma unroll
        for (int ntd = 0; ntd < 8; ntd++) {
            accO[ntd][0] *= cf0; accO[ntd][1] *= cf0;
            accO[ntd][2] *= cf1; accO[ntd][3] *= cf1;
        }

        #pragma unroll
        for (int kch = 0; kch < 4; kch++) {
            int nt0 = kch*2, nt1 = kch*2 + 1;
            uint32_t pah[4], pal[4];
            {
                float p00 = s[nt0][0], p01 = s[nt0][1], p02 = s[nt0][2], p03 = s[nt0][3];
                float p10 = s[nt1][0], p11 = s[nt1][1], p12 = s[nt1][2], p13 = s[nt1][3];
                pah[0] = packbf(p00, p01); pah[1] = packbf(p02, p03);
                pah[2] = packbf(p10, p11); pah[3] = packbf(p12, p13);
                float q00 = p00 - __bfloat162float(__float2bfloat16(p00));
                float q01 = p01 - __bfloat162float(__float2bfloat16(p01));
                float q02 = p02 - __bfloat162float(__float2bfloat16(p02));
                float q03 = p03 - __bfloat162float(__float2bfloat16(p03));
                float q10 = p10 - __bfloat162float(__float2bfloat16(p10));
                float q11 = p11 - __bfloat162float(__float2bfloat16(p11));
                float q12 = p12 - __bfloat162float(__float2bfloat16(p12));
                float q13 = p13 - __bfloat162float(__float2bfloat16(p13));
                pal[0] = packbf(q00, q01); pal[1] = packbf(q02, q03);
                pal[2] = packbf(q10, q11); pal[3] = packbf(q12, q13);
            }
            const int jo = kch*16;
            #pragma unroll
            for (int ntp = 0; ntp < 4; ntp++) {
                uint32_t offV = ((jo + lrow)*72 + ntp*16 + lkh)*2;
                uint32_t vh4[4], vl4[4];
                ldmx4t(vh4, aVh + offV);
                ldmx4t(vl4, aVl + offV);
                mma16816(accO[ntp*2],   pah, &vh4[0]);
                mma16816(accO[ntp*2],   pal, &vh4[0]);
                mma16816(accO[ntp*2],   pah, &vl4[0]);
                mma16816(accO[ntp*2+1], pah, &vh4[2]);
                mma16816(accO[ntp*2+1], pal, &vh4[2]);
                mma16816(accO[ntp*2+1], pah, &vl4[2]);
            }
        }
    }

    float inv0 = 1.0f/lr0, inv1 = 1.0f/lr1;
    #pragma unroll
    for (int ntd = 0; ntd < 8; ntd++) {
        *(float2*)&Out[((size_t)(b*Ls) + ir0)*Dm + hoff + ntd*8 + qc] =
            make_float2(accO[ntd][0]*inv0, accO[ntd][1]*inv0);
        *(float2*)&Out[((size_t)(b*Ls) + ir1)*Dm + hoff + ntd*8 + qc] =
            make_float2(accO[ntd][2]*inv1, accO[ntd][3]*inv1);
    }
}

// ---------------- combine + split comb ----------------
__global__ void combine_kernel(const float* __restrict__ pm)
{
    float a0 = pm[0], a1 = pm[1], a2 = pm[2];
    float mx = fmaxf(a0, fmaxf(a1, a2));
    float e0 = expf(a0-mx), e1 = expf(a1-mx), e2 = expf(a2-mx);
    float den = e0+e1+e2;
    float pw0 = e0/den, pw1 = e1/den;
    int e = blockIdx.x*blockDim.x + threadIdx.x;
    float v = pw0*g_outg[e] + pw1*g_outl[e];
    g_comb[e] = v;
    bsplit(v, g_combh[e], g_combl[e]);
}

// ---------------- selection path ----------------
__global__ void attns_kernel(const float* __restrict__ pm)
{
    __shared__ float sc[Ls];
    __shared__ float qs[64];
    __shared__ float red[256];
    int blk = blockIdx.x;
    int bh  = blk / NSEL, si = blk % NSEL;
    int b = bh >> 3, h = bh & 7;
    int qi = g_selidx[bh*NSEL + si];
    int t = threadIdx.x;

    if (t < 16) {
        float4 v = *(const float4*)&g_q[((size_t)(b*Ls) + qi)*Dm + h*HDim + t*4];
        *(float4*)&qs[t*4] = v;
    }
    __syncthreads();

    const float* kb = g_k + ((size_t)(b*Ls))*Dm + h*HDim;
    for (int jj = 0; jj < 8; jj++) {
        int j = t*8 + jj;
        const float4* kr = (const float4*)&kb[(size_t)j*Dm];
        float dot = 0.f;
        #pragma unroll
        for (int d4 = 0; d4 < 16; d4++) {
            float4 kv = kr[d4];
            dot = fmaf(qs[d4*4+0], kv.x, dot);
            dot = fmaf(qs[d4*4+1], kv.y, dot);
            dot = fmaf(qs[d4*4+2], kv.z, dot);
            dot = fmaf(qs[d4*4+3], kv.w, dot);
        }
        sc[j] = dot * 0.125f;
    }
    __syncthreads();

    float m = -INFINITY;
    for (int j = t; j < Ls; j += 256) m = fmaxf(m, sc[j]);
    red[t] = m; __syncthreads();
    for (int s2 = 128; s2; s2 >>= 1) { if (t < s2) red[t] = fmaxf(red[t], red[t+s2]); __syncthreads(); }
    m = red[0]; __syncthreads();

    float s = 0.f;
    for (int j = t; j < Ls; j += 256) { float e = __expf(sc[j]-m); sc[j] = e; s += e; }
    red[t] = s; __syncthreads();
    for (int s2 = 128; s2; s2 >>= 1) { if (t < s2) red[t] += red[t+s2]; __syncthreads(); }
    s = red[0]; __syncthreads();

    int d = t & 63, qtr = t >> 6;
    const float* vb = g_v + ((size_t)b*Ls)*Dm + h*HDim + d;
    float acc = 0.f;
    for (int j = qtr*512; j < qtr*512 + 512; j++)
        acc = fmaf(sc[j], vb[(size_t)j*Dm], acc);
    red[t] = acc; __syncthreads();

    if (t < 64) {
        float tot = red[t] + red[t+64] + red[t+128] + red[t+192];
        float a0 = pm[0], a1 = pm[1], a2 = pm[2];
        float mx = fmaxf(a0, fmaxf(a1, a2));
        float e0 = expf(a0-mx), e1 = expf(a1-mx), e2 = expf(a2-mx);
        float pw2 = e2/(e0+e1+e2);
        size_t idx = ((size_t)b*Ls + qi)*Dm + h*HDim + t;
        float nv = g_comb[idx] + pw2 * tot / s;
        g_comb[idx] = nv;
        bsplit(nv, g_combh[idx], g_combl[idx]);
    }
}

// ---------------- launch ----------------
extern "C" void kernel_launch(void* const* d_in, const int* in_sizes, int n_in,
                              void* d_out, int out_size)
{
    const float* query = (const float*)d_in[0];
    const float* keyi  = (const float*)d_in[1];
    const float* vali  = (const float*)d_in[2];
    const float* Wq = (const float*)d_in[3];  const float* bq = (const float*)d_in[4];
    const float* Wk = (const float*)d_in[5];  const float* bk = (const float*)d_in[6];
    const float* Wv = (const float*)d_in[7];  const float* bv = (const float*)d_in[8];
    const float* Wo = (const float*)d_in[9];  const float* bo = (const float*)d_in[10];
    const float* Wc1 = (const float*)d_in[11]; const float* bc1 = (const float*)d_in[12];
    const float* Wc2 = (const float*)d_in[13]; const float* bc2 = (const float*)d_in[14];
    const float* pm  = (const float*)d_in[15];

    __nv_bfloat16 *kcpreh, *kcprel, *hidh, *hidl, *combh, *combl, *wth, *wtl;
    __nv_bfloat16 *qh, *ql, *kh, *kl, *vh, *vl, *kch, *kcl, *vch, *vcl;
    cudaGetSymbolAddress((void**)&kcpreh, g_kcpreh);
    cudaGetSymbolAddress((void**)&kcprel, g_kcprel);
    cudaGetSymbolAddress((void**)&hidh,  g_hidh);
    cudaGetSymbolAddress((void**)&hidl,  g_hidl);
    cudaGetSymbolAddress((void**)&combh, g_combh);
    cudaGetSymbolAddress((void**)&combl, g_combl);
    cudaGetSymbolAddress((void**)&wth,   g_wth);
    cudaGetSymbolAddress((void**)&wtl,   g_wtl);
    cudaGetSymbolAddress((void**)&qh,    g_qh);
    cudaGetSymbolAddress((void**)&ql,    g_ql);
    cudaGetSymbolAddress((void**)&kh,    g_kh);
    cudaGetSymbolAddress((void**)&kl,    g_kl);
    cudaGetSymbolAddress((void**)&vh,    g_vh);
    cudaGetSymbolAddress((void**)&vl,    g_vl);
    cudaGetSymbolAddress((void**)&kch,   g_kch);
    cudaGetSymbolAddress((void**)&kcl,   g_kcl);
    cudaGetSymbolAddress((void**)&vch,   g_vch);
    cudaGetSymbolAddress((void**)&vcl,   g_vcl);

    float *outg, *outl;
    cudaGetSymbolAddress((void**)&outg,  g_outg);
    cudaGetSymbolAddress((void**)&outl,  g_outl);

    const int FLASH_SMEM = (2*128*72 + 4*64*72)*2;   // 73728
    const int SCORES_SMEM = 4*128*72*2;              // 73728
    cudaFuncSetAttribute(flash_mma_kernel, cudaFuncAttributeMaxDynamicSharedMemorySize, FLASH_SMEM);
    cudaFuncSetAttribute(scores_stats_mma_kernel, cudaFuncAttributeMaxDynamicSharedMemorySize, SCORES_SMEM);

    // prep + projections (main stream)
    split_w6_kernel<<<dim3(16,16,6), dim3(32,8)>>>(Wq, Wk, Wv, Wo, Wc1, Wc2);
    proj3_mma_kernel<<<dim3(4,32,3), 256>>>(query, keyi, vali, bq, bk, bv);

    // fork: compress+MLP branch on side stream
    cudaEventRecord(g_evA, 0);
    cudaStreamWaitEvent(g_s2, g_evA, 0);
    compress_kernel<<<512, 256, 0, g_s2>>>();
    mma_gemm64x32_kernel<<<dim3(16,16), 128, 0, g_s2>>>(
        kcpreh, kcprel, wth + 4*(size_t)Dm*Dm, wtl + 4*(size_t)Dm*Dm,
        bc1, nullptr, hidh, hidl, Dm, Dm, 1);
    mma_gemm64x32_kernel<<<dim3(16,16), 128, 0, g_s2>>>(
        hidh, hidl, wth + 5*(size_t)Dm*Dm, wtl + 5*(size_t)Dm*Dm,
        bc2, nullptr, kch, kcl, Dm, Dm, 0);
    cudaEventRecord(g_evB, g_s2);

    // scores branch (main stream, overlapped)
    scores_stats_mma_kernel<<<dim3(NJT,16,16), 256, SCORES_SMEM>>>(0.125f);
    impfinal_kernel<<<4096, 256>>>();
    topk_kernel<<<Bb*Hh, 256>>>();

    // join before flash (needs kch/vch)
    cudaStreamWaitEvent(0, g_evB, 0);

    // attention paths
    flash_mma_kernel<<<dim3(16,16,2), 256, FLASH_SMEM>>>(
        qh, ql, kh, kl, vh, vl, kch, kcl, vch, vcl, outl, outg);

    // mix + selection
    combine_kernel<<<(Bb*Ls*Dm)/256, 256>>>(pm);
    attns_kernel<<<Bb*Hh*NSEL, 256>>>(pm);

    // output projection
    mma_gemm64_kernel<<<dim3(8,64), 128>>>(combh, combl, wth + 3*(size_t)Dm*Dm, wtl + 3*(size_t)Dm*Dm,
                                           bo, (float*)d_out, nullptr, nullptr, Dm, Dm, 0);
}

// round 16
// speedup vs baseline: 1.0325x; 1.0325x over previous
#include <cuda_runtime.h>
#include <cuda_bf16.h>
#include <math.h>
#include <stdint.h>

#define Bb   2
#define Ls   2048
#define Dm   512
#define Hh   8
#define HDim 64
#define LcC  512
#define NSEL 8
#define NJT  16

// ---------------- fp32 scratch ----------------
static __device__ float g_q[Bb*Ls*Dm];
static __device__ float g_k[Bb*Ls*Dm];
static __device__ float g_v[Bb*Ls*Dm];
static __device__ float g_outg[Bb*Ls*Dm];
static __device__ float g_outl[Bb*Ls*Dm];
static __device__ float g_comb[Bb*Ls*Dm];
static __device__ float g_imp[Bb*Hh*Ls];
static __device__ int   g_selidx[Bb*Hh*NSEL];
static __device__ float g_pmax[Bb*Hh*Ls*NJT];
static __device__ float g_pse [Bb*Hh*Ls*NJT];
static __device__ float g_psum[Bb*Hh*Ls*NJT];
static __device__ float g_mlppart[4*Bb*LcC*Dm];    // split-K partials (8 MB)

// ---------------- bf16 split scratch ----------------
static __device__ __nv_bfloat16 g_wth[6][Dm*Dm];   // transposed [N][K]
static __device__ __nv_bfloat16 g_wtl[6][Dm*Dm];
static __device__ __nv_bfloat16 g_qh[Bb*Ls*Dm], g_ql[Bb*Ls*Dm];
static __device__ __nv_bfloat16 g_kh[Bb*Ls*Dm], g_kl[Bb*Ls*Dm];
static __device__ __nv_bfloat16 g_vh[Bb*Ls*Dm], g_vl[Bb*Ls*Dm];
static __device__ __nv_bfloat16 g_kch[Bb*LcC*Dm], g_kcl[Bb*LcC*Dm];
static __device__ __nv_bfloat16 g_vch[Bb*LcC*Dm], g_vcl[Bb*LcC*Dm];
static __device__ __nv_bfloat16 g_kcpreh[Bb*LcC*Dm], g_kcprel[Bb*LcC*Dm];
static __device__ __nv_bfloat16 g_hidh[Bb*LcC*Dm], g_hidl[Bb*LcC*Dm];
static __device__ __nv_bfloat16 g_combh[Bb*Ls*Dm], g_combl[Bb*Ls*Dm];

__device__ __forceinline__ void bsplit(float x, __nv_bfloat16& h, __nv_bfloat16& l)
{
    h = __float2bfloat16(x);
    l = __float2bfloat16(x - __bfloat162float(h));
}

__device__ __forceinline__ uint32_t packbf(float x, float y)
{
    __nv_bfloat162 t = __floats2bfloat162_rn(x, y);
    return *(uint32_t*)&t;
}

__device__ __forceinline__ void split2(float a, float b, uint32_t& h2, uint32_t& l2)
{
    __nv_bfloat16 ha = __float2bfloat16(a), hb = __float2bfloat16(b);
    float la = a - __bfloat162float(ha), lb = b - __bfloat162float(hb);
    __nv_bfloat162 hp; hp.x = ha; hp.y = hb;
    h2 = *(uint32_t*)&hp;
    l2 = packbf(la, lb);
}

__device__ __forceinline__ void mma16816(float* c, const uint32_t* a, const uint32_t* b)
{
    asm volatile(
        "mma.sync.aligned.m16n8k16.row.col.f32.bf16.bf16.f32 "
        "{%0,%1,%2,%3}, {%4,%5,%6,%7}, {%8,%9}, {%0,%1,%2,%3};"
        : "+f"(c[0]), "+f"(c[1]), "+f"(c[2]), "+f"(c[3])
        : "r"(a[0]), "r"(a[1]), "r"(a[2]), "r"(a[3]), "r"(b[0]), "r"(b[1]));
}

__device__ __forceinline__ uint32_t smem_u32(const void* p)
{
    uint32_t a;
    asm("{ .reg .u64 t; cvta.to.shared.u64 t, %1; cvt.u32.u64 %0, t; }" : "=r"(a) : "l"(p));
    return a;
}

__device__ __forceinline__ void ldmx4(uint32_t* r, uint32_t a)
{
    asm volatile("ldmatrix.sync.aligned.m8n8.x4.shared.b16 {%0,%1,%2,%3}, [%4];"
        : "=r"(r[0]), "=r"(r[1]), "=r"(r[2]), "=r"(r[3]) : "r"(a));
}
__device__ __forceinline__ void ldmx4t(uint32_t* r, uint32_t a)
{
    asm volatile("ldmatrix.sync.aligned.m8n8.x4.trans.shared.b16 {%0,%1,%2,%3}, [%4];"
        : "=r"(r[0]), "=r"(r[1]), "=r"(r[2]), "=r"(r[3]) : "r"(a));
}

// ---------------- prep: split + transpose all 6 weights ----------------
__global__ void split_w6_kernel(const float* w0, const float* w1, const float* w2,
                                const float* w3, const float* w4, const float* w5)
{
    __shared__ float tl[32][33];
    int widx = blockIdx.z;
    const float* w = widx==0?w0 : widx==1?w1 : widx==2?w2 : widx==3?w3 : widx==4?w4 : w5;
    int tx = threadIdx.x, ty = threadIdx.y;
    int n0 = blockIdx.x*32, k0 = blockIdx.y*32;
    #pragma unroll
    for (int i = 0; i < 4; i++)
        tl[ty + i*8][tx] = w[(size_t)(k0 + ty + i*8)*Dm + n0 + tx];
    __syncthreads();
    #pragma unroll
    for (int i = 0; i < 4; i++) {
        float v = tl[tx][ty + i*8];
        size_t o = (size_t)(n0 + ty + i*8)*Dm + k0 + tx;
        bsplit(v, g_wth[widx][o], g_wtl[widx][o]);
    }
}

// =========================================================================
// 64x64-tile bf16x3 GEMM, depth-2 pipelined (3-stage smem ring). Outproj.
// =========================================================================
__global__ void __launch_bounds__(128, 4) mma_gemm64_kernel(
    const __nv_bfloat16* __restrict__ Ah, const __nv_bfloat16* __restrict__ Al,
    const __nv_bfloat16* __restrict__ Bh, const __nv_bfloat16* __restrict__ Bl,
    const float* __restrict__ bias, float* __restrict__ C,
    __nv_bfloat16* __restrict__ Ch, __nv_bfloat16* __restrict__ Cl,
    int N, int K, int gelu)
{
    __shared__ __nv_bfloat16 sAh[3][64*24], sAl[3][64*24];
    __shared__ __nv_bfloat16 sBh[3][64*24], sBl[3][64*24];
    const int tid = threadIdx.x;
    const int lane = tid & 31, warp = tid >> 5;
    const int wm = warp >> 1, wn = warp & 1;
    const int qr = lane >> 2, qc = (lane & 3)*2;
    const int lrow = lane & 15, lkh = (lane >> 4)*8;
    const int row0 = blockIdx.y*64, col0 = blockIdx.x*64;
    const int half = tid >> 6, r = tid & 63;

    const __nv_bfloat16* As = half ? Al : Ah;
    const __nv_bfloat16* Bs = half ? Bl : Bh;
    const int nk = K >> 4;

    {
        const uint4* pa = (const uint4*)(As + (size_t)(row0 + r)*K);
        const uint4* pb = (const uint4*)(Bs + (size_t)(col0 + r)*K);
        uint4 a0 = pa[0], a1 = pa[1], b0 = pb[0], b1 = pb[1];
        __nv_bfloat16* dA = half ? sAl[0] : sAh[0];
        __nv_bfloat16* dB = half ? sBl[0] : sBh[0];
        *(uint4*)&dA[r*24]     = a0; *(uint4*)&dA[r*24 + 8] = a1;
        *(uint4*)&dB[r*24]     = b0; *(uint4*)&dB[r*24 + 8] = b1;
    }
    uint4 Rna0, Rna1, Rnb0, Rnb1;
    if (nk > 1) {
        const uint4* pa = (const uint4*)(As + (size_t)(row0 + r)*K + 16);
        const uint4* pb = (const uint4*)(Bs + (size_t)(col0 + r)*K + 16);
        Rna0 = pa[0]; Rna1 = pa[1]; Rnb0 = pb[0]; Rnb1 = pb[1];
    }
    __syncthreads();

    float acc[2][4][4] = {};
    for (int kc = 0; kc < nk; kc++) {
        if (kc + 1 < nk) {
            const int sb = (kc + 1) % 3;
            __nv_bfloat16* dA = half ? sAl[sb] : sAh[sb];
            __nv_bfloat16* dB = half ? sBl[sb] : sBh[sb];
            *(uint4*)&dA[r*24]     = Rna0; *(uint4*)&dA[r*24 + 8] = Rna1;
            *(uint4*)&dB[r*24]     = Rnb0; *(uint4*)&dB[r*24 + 8] = Rnb1;
        }
        if (kc + 2 < nk) {
            int k0 = (kc + 2)*16;
            const uint4* pa = (const uint4*)(As + (size_t)(row0 + r)*K + k0);
            const uint4* pb = (const uint4*)(Bs + (size_t)(col0 + r)*K + k0);
            Rna0 = pa[0]; Rna1 = pa[1]; Rnb0 = pb[0]; Rnb1 = pb[1];
        }
        __syncthreads();

        const int buf = kc % 3;
        const uint32_t cAh = smem_u32(&sAh[buf][0]);
        const uint32_t cAl = smem_u32(&sAl[buf][0]);
        const uint32_t cBh = smem_u32(&sBh[buf][0]);
        const uint32_t cBl = smem_u32(&sBl[buf][0]);

        uint32_t bh[4][2], bl[4][2];
        #pragma unroll
        for (int ntp = 0; ntp < 2; ntp++) {
            uint32_t off = (uint32_t)(((wn*32 + ntp*16 + lrow)*24 + lkh)*2);
            uint32_t t4[4], u4[4];
            ldmx4(t4, cBh + off);
            ldmx4(u4, cBl + off);
            bh[ntp*2][0]   = t4[0]; bh[ntp*2][1]   = t4[2];
            bh[ntp*2+1][0] = t4[1]; bh[ntp*2+1][1] = t4[3];
            bl[ntp*2][0]   = u4[0]; bl[ntp*2][1]   = u4[2];
            bl[ntp*2+1][0] = u4[1]; bl[ntp*2+1][1] = u4[3];
        }
        #pragma unroll
        for (int mt = 0; mt < 2; mt++) {
            uint32_t offA = (uint32_t)(((wm*32 + mt*16 + lrow)*24 + lkh)*2);
            uint32_t ah[4], al[4];
            ldmx4(ah, cAh + offA);
            ldmx4(al, cAl + offA);
            #pragma unroll
            for (int nt = 0; nt < 4; nt++) {
                mma16816(acc[mt][nt], ah, bh[nt]);
                mma16816(acc[mt][nt], ah, bl[nt]);
                mma16816(acc[mt][nt], al, bh[nt]);
            }
        }
    }

    #pragma unroll
    for (int mt = 0; mt < 2; mt++) {
        int gr = row0 + wm*32 + mt*16 + qr;
        #pragma unroll
        for (int nt = 0; nt < 4; nt++) {
            int gc = col0 + wn*32 + nt*8 + qc;
            float v0 = acc[mt][nt][0] + bias[gc];
            float v1 = acc[mt][nt][1] + bias[gc+1];
            float v2 = acc[mt][nt][2] + bias[gc];
            float v3 = acc[mt][nt][3] + bias[gc+1];
            if (gelu) {
                v0 = 0.5f*v0*(1.0f + erff(v0*0.70710678118654752f));
                v1 = 0.5f*v1*(1.0f + erff(v1*0.70710678118654752f));
                v2 = 0.5f*v2*(1.0f + erff(v2*0.70710678118654752f));
                v3 = 0.5f*v3*(1.0f + erff(v3*0.70710678118654752f));
            }
            if (C) {
                *(float2*)&C[(size_t)gr*N + gc]     = make_float2(v0, v1);
                *(float2*)&C[(size_t)(gr+8)*N + gc] = make_float2(v2, v3);
            }
            if (Ch) {
                uint32_t h01, l01, h23, l23;
                split2(v0, v1, h01, l01);
                split2(v2, v3, h23, l23);
                *(uint32_t*)&Ch[(size_t)gr*N + gc]     = h01;
                *(uint32_t*)&Cl[(size_t)gr*N + gc]     = l01;
                *(uint32_t*)&Ch[(size_t)(gr+8)*N + gc] = h23;
                *(uint32_t*)&Cl[(size_t)(gr+8)*N + gc] = l23;
            }
        }
    }
}

// =========================================================================
// 64x64-tile bf16x3 GEMM, split-K=4 (MLP GEMMs). z = K-slice; fp32 partials.
// (R12-measured: 18us at grid 512.)
// =========================================================================
__global__ void __launch_bounds__(128, 4) mma_gemm64_sk_kernel(
    const __nv_bfloat16* __restrict__ Ah, const __nv_bfloat16* __restrict__ Al,
    const __nv_bfloat16* __restrict__ Bh, const __nv_bfloat16* __restrict__ Bl,
    float* __restrict__ Cp, int N, int K)
{
    __shared__ __nv_bfloat16 sAh[2][64*24], sAl[2][64*24];
    __shared__ __nv_bfloat16 sBh[2][64*24], sBl[2][64*24];
    const int tid = threadIdx.x;
    const int lane = tid & 31, warp = tid >> 5;
    const int wm = warp >> 1, wn = warp & 1;
    const int qr = lane >> 2, qc = (lane & 3)*2;
    const int lrow = lane & 15, lkh = (lane >> 4)*8;
    const int row0 = blockIdx.y*64, col0 = blockIdx.x*64;
    const int half = tid >> 6, r = tid & 63;
    const int Ksl = K >> 2;
    const int kbase = blockIdx.z * Ksl;
    const int M = gridDim.y * 64;

    const __nv_bfloat16* As = (half ? Al : Ah) + kbase;
    const __nv_bfloat16* Bs = (half ? Bl : Bh) + kbase;

    {
        const uint4* pa = (const uint4*)(As + (size_t)(row0 + r)*K);
        const uint4* pb = (const uint4*)(Bs + (size_t)(col0 + r)*K);
        uint4 a0 = pa[0], a1 = pa[1], b0 = pb[0], b1 = pb[1];
        __nv_bfloat16* dA = half ? sAl[0] : sAh[0];
        __nv_bfloat16* dB = half ? sBl[0] : sBh[0];
        *(uint4*)&dA[r*24]     = a0; *(uint4*)&dA[r*24 + 8] = a1;
        *(uint4*)&dB[r*24]     = b0; *(uint4*)&dB[r*24 + 8] = b1;
    }
    __syncthreads();

    float acc[2][4][4] = {};
    const int nk = Ksl >> 4;
    for (int kc = 0; kc < nk; kc++) {
        const int buf = kc & 1;
        uint4 na0, na1, nb0, nb1;
        if (kc + 1 < nk) {
            int k0 = (kc + 1)*16;
            const uint4* pa = (const uint4*)(As + (size_t)(row0 + r)*K + k0);
            const uint4* pb = (const uint4*)(Bs + (size_t)(col0 + r)*K + k0);
            na0 = pa[0]; na1 = pa[1]; nb0 = pb[0]; nb1 = pb[1];
        }

        const uint32_t cAh = smem_u32(&sAh[buf][0]);
        const uint32_t cAl = smem_u32(&sAl[buf][0]);
        const uint32_t cBh = smem_u32(&sBh[buf][0]);
        const uint32_t cBl = smem_u32(&sBl[buf][0]);

        uint32_t bh[4][2], bl[4][2];
        #pragma unroll
        for (int ntp = 0; ntp < 2; ntp++) {
            uint32_t off = (uint32_t)(((wn*32 + ntp*16 + lrow)*24 + lkh)*2);
            uint32_t t4[4], u4[4];
            ldmx4(t4, cBh + off);
            ldmx4(u4, cBl + off);
            bh[ntp*2][0]   = t4[0]; bh[ntp*2][1]   = t4[2];
            bh[ntp*2+1][0] = t4[1]; bh[ntp*2+1][1] = t4[3];
            bl[ntp*2][0]   = u4[0]; bl[ntp*2][1]   = u4[2];
            bl[ntp*2+1][0] = u4[1]; bl[ntp*2+1][1] = u4[3];
        }
        #pragma unroll
        for (int mt = 0; mt < 2; mt++) {
            uint32_t offA = (uint32_t)(((wm*32 + mt*16 + lrow)*24 + lkh)*2);
            uint32_t ah[4], al[4];
            ldmx4(ah, cAh + offA);
            ldmx4(al, cAl + offA);
            #pragma unroll
            for (int nt = 0; nt < 4; nt++) {
                mma16816(acc[mt][nt], ah, bh[nt]);
                mma16816(acc[mt][nt], ah, bl[nt]);
                mma16816(acc[mt][nt], al, bh[nt]);
            }
        }

        if (kc + 1 < nk) {
            const int nb = buf ^ 1;
            __nv_bfloat16* dA = half ? sAl[nb] : sAh[nb];
            __nv_bfloat16* dB = half ? sBl[nb] : sBh[nb];
            *(uint4*)&dA[r*24]     = na0; *(uint4*)&dA[r*24 + 8] = na1;
            *(uint4*)&dB[r*24]     = nb0; *(uint4*)&dB[r*24 + 8] = nb1;
        }
        __syncthreads();
    }

    float* dst = Cp + (size_t)blockIdx.z * M * N;
    #pragma unroll
    for (int mt = 0; mt < 2; mt++) {
        int gr = row0 + wm*32 + mt*16 + qr;
        #pragma unroll
        for (int nt = 0; nt < 4; nt++) {
            int gc = col0 + wn*32 + nt*8 + qc;
            *(float2*)&dst[(size_t)gr*N + gc]     = make_float2(acc[mt][nt][0], acc[mt][nt][1]);
            *(float2*)&dst[(size_t)(gr+8)*N + gc] = make_float2(acc[mt][nt][2], acc[mt][nt][3]);
        }
    }
}

// reduce split-K partials: sum 4 + bias (+gelu) -> hi/lo splits
__global__ void mlpreduce_kernel(const float* __restrict__ bias, int gelu,
                                 __nv_bfloat16* __restrict__ Ch, __nv_bfloat16* __restrict__ Cl)
{
    const int total = Bb*LcC*Dm;
    int i2 = (blockIdx.x*blockDim.x + threadIdx.x)*2;
    float2 p0 = *(const float2*)&g_mlppart[i2];
    float2 p1 = *(const float2*)&g_mlppart[total + i2];
    float2 p2 = *(const float2*)&g_mlppart[2*total + i2];
    float2 p3 = *(const float2*)&g_mlppart[3*total + i2];
    int col = i2 & (Dm - 1);
    float v0 = ((p0.x + p1.x) + (p2.x + p3.x)) + bias[col];
    float v1 = ((p0.y + p1.y) + (p2.y + p3.y)) + bias[col + 1];
    if (gelu) {
        v0 = 0.5f*v0*(1.0f + erff(v0*0.70710678118654752f));
        v1 = 0.5f*v1*(1.0f + erff(v1*0.70710678118654752f));
    }
    uint32_t h2, l2;
    split2(v0, v1, h2, l2);
    *(uint32_t*)&Ch[i2] = h2;
    *(uint32_t*)&Cl[i2] = l2;
}

// =========================================================================
// bf16x3 GEMM with fused fp32->hi/lo A conversion (projections), 128x128.
// =========================================================================
__device__ __forceinline__ void mma_gemm_f32A_body(
    const float* __restrict__ Afp,
    const __nv_bfloat16* __restrict__ Bh, const __nv_bfloat16* __restrict__ Bl,
    const float* __restrict__ bias, float* __restrict__ C,
    __nv_bfloat16* __restrict__ Ch, __nv_bfloat16* __restrict__ Cl,
    int N, int K)
{
    __shared__ __nv_bfloat16 sAh[2][128*24], sAl[2][128*24];
    __shared__ __nv_bfloat16 sBh[2][128*24], sBl[2][128*24];
    const int tid = threadIdx.x;
    const int lane = tid & 31, warp = tid >> 5;
    const int wm = warp >> 2, wn = warp & 3;
    const int qr = lane >> 2, qc = (lane & 3)*2;
    const int lrow = lane & 15, lkh = (lane >> 4)*8;
    const int row0 = blockIdx.y*128, col0 = blockIdx.x*128;
    const int half = tid >> 7, r = tid & 127;

    if (half == 0) {
        const float4* pa = (const float4*)(Afp + (size_t)(row0 + r)*K);
        float4 f0 = pa[0], f1 = pa[1], f2 = pa[2], f3 = pa[3];
        float fv[16] = {f0.x,f0.y,f0.z,f0.w, f1.x,f1.y,f1.z,f1.w,
                        f2.x,f2.y,f2.z,f2.w, f3.x,f3.y,f3.z,f3.w};
        #pragma unroll
        for (int c2 = 0; c2 < 8; c2++) {
            uint32_t h2, l2;
            split2(fv[c2*2], fv[c2*2+1], h2, l2);
            *(uint32_t*)&sAh[0][r*24 + c2*2] = h2;
            *(uint32_t*)&sAl[0][r*24 + c2*2] = l2;
        }
    } else {
        const uint4* pbh = (const uint4*)(Bh + (size_t)(col0 + r)*K);
        const uint4* pbl = (const uint4*)(Bl + (size_t)(col0 + r)*K);
        uint4 b0 = pbh[0], b1 = pbh[1], c0 = pbl[0], c1 = pbl[1];
        *(uint4*)&sBh[0][r*24]     = b0; *(uint4*)&sBh[0][r*24 + 8] = b1;
        *(uint4*)&sBl[0][r*24]     = c0; *(uint4*)&sBl[0][r*24 + 8] = c1;
    }
    __syncthreads();

    float acc[4][4][4] = {};
    const int nk = K >> 4;
    for (int kc = 0; kc < nk; kc++) {
        const int buf = kc & 1;
        float nfv[16];
        uint4 nb0, nb1, nc0, nc1;
        if (kc + 1 < nk) {
            int k0 = (kc + 1)*16;
            if (half == 0) {
                const float4* pa = (const float4*)(Afp + (size_t)(row0 + r)*K + k0);
                float4 f0 = pa[0], f1 = pa[1], f2 = pa[2], f3 = pa[3];
                nfv[0]=f0.x; nfv[1]=f0.y; nfv[2]=f0.z; nfv[3]=f0.w;
                nfv[4]=f1.x; nfv[5]=f1.y; nfv[6]=f1.z; nfv[7]=f1.w;
                nfv[8]=f2.x; nfv[9]=f2.y; nfv[10]=f2.z; nfv[11]=f2.w;
                nfv[12]=f3.x; nfv[13]=f3.y; nfv[14]=f3.z; nfv[15]=f3.w;
            } else {
                const uint4* pbh = (const uint4*)(Bh + (size_t)(col0 + r)*K + k0);
                const uint4* pbl = (const uint4*)(Bl + (size_t)(col0 + r)*K + k0);
                nb0 = pbh[0]; nb1 = pbh[1]; nc0 = pbl[0]; nc1 = pbl[1];
            }
        }

        const uint32_t cAh = smem_u32(&sAh[buf][0]);
        const uint32_t cAl = smem_u32(&sAl[buf][0]);
        const uint32_t cBh = smem_u32(&sBh[buf][0]);
        const uint32_t cBl = smem_u32(&sBl[buf][0]);

        uint32_t bh[4][2], bl[4][2];
        #pragma unroll
        for (int ntp = 0; ntp < 2; ntp++) {
            uint32_t off = (uint32_t)(((wn*32 + ntp*16 + lrow)*24 + lkh)*2);
            uint32_t t4[4], u4[4];
            ldmx4(t4, cBh + off);
            ldmx4(u4, cBl + off);
            bh[ntp*2][0]   = t4[0]; bh[ntp*2][1]   = t4[2];
            bh[ntp*2+1][0] = t4[1]; bh[ntp*2+1][1] = t4[3];
            bl[ntp*2][0]   = u4[0]; bl[ntp*2][1]   = u4[2];
            bl[ntp*2+1][0] = u4[1]; bl[ntp*2+1][1] = u4[3];
        }
        #pragma unroll
        for (int mt = 0; mt < 4; mt++) {
            uint32_t offA = (uint32_t)(((wm*64 + mt*16 + lrow)*24 + lkh)*2);
            uint32_t ah[4], al[4];
            ldmx4(ah, cAh + offA);
            ldmx4(al, cAl + offA);
            #pragma unroll
            for (int nt = 0; nt < 4; nt++) {
                mma16816(acc[mt][nt], ah, bh[nt]);
                mma16816(acc[mt][nt], ah, bl[nt]);
                mma16816(acc[mt][nt], al, bh[nt]);
            }
        }

        if (kc + 1 < nk) {
            const int nb = buf ^ 1;
            if (half == 0) {
                #pragma unroll
                for (int c2 = 0; c2 < 8; c2++) {
                    uint32_t h2, l2;
                    split2(nfv[c2*2], nfv[c2*2+1], h2, l2);
                    *(uint32_t*)&sAh[nb][r*24 + c2*2] = h2;
                    *(uint32_t*)&sAl[nb][r*24 + c2*2] = l2;
                }
            } else {
                *(uint4*)&sBh[nb][r*24]     = nb0; *(uint4*)&sBh[nb][r*24 + 8] = nb1;
                *(uint4*)&sBl[nb][r*24]     = nc0; *(uint4*)&sBl[nb][r*24 + 8] = nc1;
            }
        }
        __syncthreads();
    }

    #pragma unroll
    for (int mt = 0; mt < 4; mt++) {
        int gr = row0 + wm*64 + mt*16 + qr;
        #pragma unroll
        for (int nt = 0; nt < 4; nt++) {
            int gc = col0 + wn*32 + nt*8 + qc;
            float v0 = acc[mt][nt][0] + bias[gc];
            float v1 = acc[mt][nt][1] + bias[gc+1];
            float v2 = acc[mt][nt][2] + bias[gc];
            float v3 = acc[mt][nt][3] + bias[gc+1];
            if (C) {
                *(float2*)&C[(size_t)gr*N + gc]     = make_float2(v0, v1);
                *(float2*)&C[(size_t)(gr+8)*N + gc] = make_float2(v2, v3);
            }
            if (Ch) {
                uint32_t h01, l01, h23, l23;
                split2(v0, v1, h01, l01);
                split2(v2, v3, h23, l23);
                *(uint32_t*)&Ch[(size_t)gr*N + gc]     = h01;
                *(uint32_t*)&Cl[(size_t)gr*N + gc]     = l01;
                *(uint32_t*)&Ch[(size_t)(gr+8)*N + gc] = h23;
                *(uint32_t*)&Cl[(size_t)(gr+8)*N + gc] = l23;
            }
        }
    }
}

__global__ void __launch_bounds__(256, 2) proj3_mma_kernel(
    const float* q_in, const float* k_in, const float* v_in,
    const float* bq, const float* bk, const float* bv)
{
    int z = blockIdx.z;
    if (z == 0)
        mma_gemm_f32A_body(q_in, g_wth[0], g_wtl[0], bq, g_q, g_qh, g_ql, Dm, Dm);
    else if (z == 1)
        mma_gemm_f32A_body(k_in, g_wth[1], g_wtl[1], bk, g_k, g_kh, g_kl, Dm, Dm);
    else
        mma_gemm_f32A_body(v_in, g_wth[2], g_wtl[2], bv, g_v, g_vh, g_vl, Dm, Dm);
}

// =========================================================================
// dense QK^T (bf16x3 mma) + fused row stats, ldmatrix fragments
// =========================================================================
extern __shared__ __nv_bfloat16 scsm[];
__global__ void __launch_bounds__(256, 2) scores_stats_mma_kernel(float scale)
{
    __nv_bfloat16* sAh = scsm;
    __nv_bfloat16* sAl = scsm + 128*72;
    __nv_bfloat16* sBh = scsm + 2*128*72;
    __nv_bfloat16* sBl = scsm + 3*128*72;
    __shared__ float s4a[128][4], s4b[128][4], srm[128];

    const int tid = threadIdx.x;
    const int lane = tid & 31, warp = tid >> 5;
    const int wm = warp >> 2, wn = warp & 3;
    const int qr = lane >> 2;
    const int bh = blockIdx.z;
    const int b = bh >> 3, h = bh & 7;
    const int i0 = blockIdx.y*128, j0 = blockIdx.x*128;

    const __nv_bfloat16* Qhp = g_qh + ((size_t)(b*Ls) + i0)*Dm + h*HDim;
    const __nv_bfloat16* Qlp = g_ql + ((size_t)(b*Ls) + i0)*Dm + h*HDim;
    const __nv_bfloat16* Khp = g_kh + ((size_t)(b*Ls) + j0)*Dm + h*HDim;
    const __nv_bfloat16* Klp = g_kl + ((size_t)(b*Ls) + j0)*Dm + h*HDim;

    #pragma unroll
    for (int i = 0; i < 4; i++) {
        int slot = tid*4 + i;
        int row = slot >> 3, c = slot & 7;
        *(uint4*)&sAh[row*72 + c*8] = *(const uint4*)&Qhp[(size_t)row*Dm + c*8];
        *(uint4*)&sAl[row*72 + c*8] = *(const uint4*)&Qlp[(size_t)row*Dm + c*8];
        *(uint4*)&sBh[row*72 + c*8] = *(const uint4*)&Khp[(size_t)row*Dm + c*8];
        *(uint4*)&sBl[row*72 + c*8] = *(const uint4*)&Klp[(size_t)row*Dm + c*8];
    }
    __syncthreads();

    const uint32_t sc0 = smem_u32(scsm);
    const uint32_t aAh = sc0, aAl = sc0 + 128*72*2, aBh = sc0 + 2*128*72*2, aBl = sc0 + 3*128*72*2;
    const int lrow = lane & 15, lkh = (lane >> 4)*8;

    float acc[4][4][4] = {};
    #pragma unroll
    for (int kc = 0; kc < 4; kc++) {
        const int ko = kc*16;
        uint32_t Bh4[2][4], Bl4[2][4];
        #pragma unroll
        for (int ntp = 0; ntp < 2; ntp++) {
            uint32_t off = ((wn*32 + ntp*16 + lrow)*72 + ko + lkh)*2;
            ldmx4(Bh4[ntp], aBh + off);
            ldmx4(Bl4[ntp], aBl + off);
        }
        #pragma unroll
        for (int mt = 0; mt < 4; mt++) {
            uint32_t offA = ((wm*64 + mt*16 + lrow)*72 + ko + lkh)*2;
            uint32_t ah[4], al[4];
            ldmx4(ah, aAh + offA);
            ldmx4(al, aAl + offA);
            #pragma unroll
            for (int nt = 0; nt < 4; nt++) {
                uint32_t bhf[2] = { Bh4[nt>>1][nt&1], Bh4[nt>>1][(nt&1)+2] };
                uint32_t blf[2] = { Bl4[nt>>1][nt&1], Bl4[nt>>1][(nt&1)+2] };
                mma16816(acc[mt][nt], ah, bhf);
                mma16816(acc[mt][nt], ah, blf);
                mma16816(acc[mt][nt], al, bhf);
            }
        }
    }

    #pragma unroll
    for (int mt = 0; mt < 4; mt++) {
        float m0 = -INFINITY, m1 = -INFINITY;
        #pragma unroll
        for (int nt = 0; nt < 4; nt++) {
            m0 = fmaxf(m0, fmaxf(acc[mt][nt][0], acc[mt][nt][1]));
            m1 = fmaxf(m1, fmaxf(acc[mt][nt][2], acc[mt][nt][3]));
        }
        m0 = fmaxf(m0, __shfl_xor_sync(0xFFFFFFFFu, m0, 1));
        m0 = fmaxf(m0, __shfl_xor_sync(0xFFFFFFFFu, m0, 2));
        m1 = fmaxf(m1, __shfl_xor_sync(0xFFFFFFFFu, m1, 1));
        m1 = fmaxf(m1, __shfl_xor_sync(0xFFFFFFFFu, m1, 2));
        if ((lane & 3) == 0) {
            s4a[wm*64 + mt*16 + qr][wn]     = m0;
            s4a[wm*64 + mt*16 + 8 + qr][wn] = m1;
        }
    }
    __syncthreads();
    if (tid < 128)
        srm[tid] = fmaxf(fmaxf(s4a[tid][0], s4a[tid][1]), fmaxf(s4a[tid][2], s4a[tid][3]));
    __syncthreads();

    #pragma unroll
    for (int mt = 0; mt < 4; mt++) {
        int lr0 = wm*64 + mt*16 + qr, lr1 = lr0 + 8;
        float rm0 = srm[lr0]*scale, rm1 = srm[lr1]*scale;
        float se0 = 0.f, se1 = 0.f, ss0 = 0.f, ss1 = 0.f;
        #pragma unroll
        for (int nt = 0; nt < 4; nt++) {
            float x0 = acc[mt][nt][0]*scale, x1 = acc[mt][nt][1]*scale;
            float x2 = acc[mt][nt][2]*scale, x3 = acc[mt][nt][3]*scale;
            se0 += __expf(x0 - rm0) + __expf(x1 - rm0);
            se1 += __expf(x2 - rm1) + __expf(x3 - rm1);
            ss0 += x0 + x1; ss1 += x2 + x3;
        }
        se0 += __shfl_xor_sync(0xFFFFFFFFu, se0, 1); se0 += __shfl_xor_sync(0xFFFFFFFFu, se0, 2);
        se1 += __shfl_xor_sync(0xFFFFFFFFu, se1, 1); se1 += __shfl_xor_sync(0xFFFFFFFFu, se1, 2);
        ss0 += __shfl_xor_sync(0xFFFFFFFFu, ss0, 1); ss0 += __shfl_xor_sync(0xFFFFFFFFu, ss0, 2);
        ss1 += __shfl_xor_sync(0xFFFFFFFFu, ss1, 1); ss1 += __shfl_xor_sync(0xFFFFFFFFu, ss1, 2);
        if ((lane & 3) == 0) {
            s4b[lr0][wn] = se0; s4b[lr1][wn] = se1;
            s4a[lr0][wn] = ss0; s4a[lr1][wn] = ss1;
        }
    }
    __syncthreads();
    if (tid < 128) {
        int rowg = bh*Ls + i0 + tid;
        int jt = blockIdx.x;
        g_pmax[(size_t)rowg*NJT + jt] = srm[tid]*scale;
        g_pse [(size_t)rowg*NJT + jt] = s4b[tid][0]+s4b[tid][1]+s4b[tid][2]+s4b[tid][3];
        g_psum[(size_t)rowg*NJT + jt] = s4a[tid][0]+s4a[tid][1]+s4a[tid][2]+s4a[tid][3];
    }
}

// ---------------- compress: mean of 4 rows -> splits ----------------
__global__ void compress_kernel()
{
    int e4 = blockIdx.x*blockDim.x + threadIdx.x;
    int b = e4 / (LcC*Dm/4);
    int r = e4 % (LcC*Dm/4);
    int m = r / (Dm/4), d4 = r % (Dm/4);
    const float4* k4 = (const float4*)g_k;
    const float4* v4 = (const float4*)g_v;
    size_t base = ((size_t)(b*Ls + m*4)*Dm)/4 + d4;
    float4 a = k4[base], bb = k4[base+128], c = k4[base+256], d = k4[base+384];
    float ox = 0.25f*(a.x+bb.x+c.x+d.x), oy = 0.25f*(a.y+bb.y+c.y+d.y);
    float oz = 0.25f*(a.z+bb.z+c.z+d.z), ow = 0.25f*(a.w+bb.w+c.w+d.w);
    bsplit(ox, g_kcpreh[e4*4+0], g_kcprel[e4*4+0]);
    bsplit(oy, g_kcpreh[e4*4+1], g_kcprel[e4*4+1]);
    bsplit(oz, g_kcpreh[e4*4+2], g_kcprel[e4*4+2]);
    bsplit(ow, g_kcpreh[e4*4+3], g_kcprel[e4*4+3]);
    a = v4[base]; bb = v4[base+128]; c = v4[base+256]; d = v4[base+384];
    ox = 0.25f*(a.x+bb.x+c.x+d.x); oy = 0.25f*(a.y+bb.y+c.y+d.y);
    oz = 0.25f*(a.z+bb.z+c.z+d.z); ow = 0.25f*(a.w+bb.w+c.w+d.w);
    bsplit(ox, g_vch[e4*4+0], g_vcl[e4*4+0]);
    bsplit(oy, g_vch[e4*4+1], g_vcl[e4*4+1]);
    bsplit(oz, g_vch[e4*4+2], g_vcl[e4*4+2]);
    bsplit(ow, g_vch[e4*4+3], g_vcl[e4*4+3]);
}

// ---------------- importance merge ----------------
__global__ void impfinal_kernel()
{
    int warp = (blockIdx.x*blockDim.x + threadIdx.x) >> 5;
    int lane = threadIdx.x & 31;
    float pm = -INFINITY, pe = 0.f, ps = 0.f;
    if (lane < NJT) {
        pm = g_pmax[(size_t)warp*NJT + lane];
        pe = g_pse [(size_t)warp*NJT + lane];
        ps = g_psum[(size_t)warp*NJT + lane];
    }
    float m = pm;
    #pragma unroll
    for (int o = 8; o; o >>= 1) m = fmaxf(m, __shfl_xor_sync(0xFFFFFFFFu, m, o));
    float se = (lane < NJT) ? pe * __expf(pm - m) : 0.f;
    #pragma unroll
    for (int o = 8; o; o >>= 1) {
        se += __shfl_xor_sync(0xFFFFFFFFu, se, o);
        ps += __shfl_xor_sync(0xFFFFFFFFu, ps, o);
    }
    if (lane == 0)
        g_imp[warp] = m + logf(se) - 7.6246189861593985f - ps * (1.0f/2048.0f);
}

// ---------------- top-8 ----------------
__global__ void topk_kernel()
{
    int bh = blockIdx.x;
    const float* imp = g_imp + bh*Ls;
    __shared__ float bv[256];
    __shared__ int   bi[256];
    __shared__ int   chosen[NSEL];
    int t = threadIdx.x;
    for (int itu = 0; itu < NSEL; itu++) {
        float best = -INFINITY; int bidx = 0x7FFFFFFF;
        for (int j = t; j < Ls; j += 256) {
            bool skip = false;
            for (int c = 0; c < itu; c++) if (chosen[c] == j) skip = true;
            if (skip) continue;
            float vv = imp[j];
            if (vv > best || (vv == best && j < bidx)) { best = vv; bidx = j; }
        }
        bv[t] = best; bi[t] = bidx;
        __syncthreads();
        for (int s2 = 128; s2; s2 >>= 1) {
            if (t < s2) {
                if (bv[t+s2] > bv[t] || (bv[t+s2] == bv[t] && bi[t+s2] < bi[t])) {
                    bv[t] = bv[t+s2]; bi[t] = bi[t+s2];
                }
            }
            __syncthreads();
        }
        if (t == 0) { chosen[itu] = bi[0]; g_selidx[bh*NSEL + itu] = bi[0]; }
        __syncthreads();
    }
}

// =========================================================================
// fused flash attention, 128-row Q tiles, 8 warps all in M, band chunk skip.
// =========================================================================
extern __shared__ char fsm2[];
__global__ void __launch_bounds__(256, 2) flash_mma_kernel(
    const __nv_bfloat16* __restrict__ Qh, const __nv_bfloat16* __restrict__ Ql,
    const __nv_bfloat16* __restrict__ Khg, const __nv_bfloat16* __restrict__ Klg,
    const __nv_bfloat16* __restrict__ Vhg, const __nv_bfloat16* __restrict__ Vlg,
    const __nv_bfloat16* __restrict__ Khc, const __nv_bfloat16* __restrict__ Klc,
    const __nv_bfloat16* __restrict__ Vhc, const __nv_bfloat16* __restrict__ Vlc,
    float* __restrict__ OutL, float* __restrict__ OutG)
{
    __nv_bfloat16* sQh = (__nv_bfloat16*)fsm2;   // [128][72]
    __nv_bfloat16* sQl = sQh + 128*72;
    __nv_bfloat16* sKh = sQl + 128*72;           // [64][72]
    __nv_bfloat16* sKl = sKh + 64*72;
    __nv_bfloat16* sVh = sKl + 64*72;            // natural [j][d]
    __nv_bfloat16* sVl = sVh + 64*72;

    const int z = blockIdx.z;
    const __nv_bfloat16* Kh = z ? Khc : Khg;
    const __nv_bfloat16* Kl = z ? Klc : Klg;
    const __nv_bfloat16* Vh = z ? Vhc : Vhg;
    const __nv_bfloat16* Vl = z ? Vlc : Vlg;
    float* Out = z ? OutG : OutL;
    const int LK = z ? LcC : Ls;
    const int nchunks = z ? 8 : 4;
    const int local = z ? 0 : 1;

    const int tid = threadIdx.x;
    const int lane = tid & 31, w = tid >> 5;
    const int qr = lane >> 2, qc = (lane & 3)*2;
    const int lrow = lane & 15, lkh = (lane >> 4)*8;
    const int bh = blockIdx.y;
    const int b = bh >> 3, h = bh & 7;
    const int i0 = blockIdx.x*128;
    const size_t hoff = (size_t)h*HDim;

    const uint32_t sb = smem_u32(fsm2);
    const uint32_t aQh = sb, aQl = sb + 18432;
    const uint32_t aKh = sb + 36864, aKl = sb + 46080;
    const uint32_t aVh = sb + 55296, aVl = sb + 64512;

    {
        int row = tid >> 1, part = (tid & 1)*32;
        const uint4* ph = (const uint4*)(Qh + ((size_t)(b*Ls) + i0 + row)*Dm + hoff + part);
        const uint4* pl = (const uint4*)(Ql + ((size_t)(b*Ls) + i0 + row)*Dm + hoff + part);
        #pragma unroll
        for (int j = 0; j < 4; j++) {
            *(uint4*)&sQh[row*72 + part + j*8] = ph[j];
            *(uint4*)&sQl[row*72 + part + j*8] = pl[j];
        }
    }

    float accO[8][4] = {};
    float mr0 = -INFINITY, mr1 = -INFINITY;
    float lr0 = 0.f, lr1 = 0.f;
    const int ir0 = i0 + w*16 + qr, ir1 = ir0 + 8;

    for (int c = 0; c < nchunks; c++) {
        int jbase = (local ? i0 - 64 : 0) + c*64;
        __syncthreads();
        {
            int row = tid >> 2, c16 = (tid & 3)*16;
            int jg = jbase + row;
            uint4 kh0 = {0,0,0,0}, kh1 = {0,0,0,0}, kl0 = {0,0,0,0}, kl1 = {0,0,0,0};
            uint4 vh0 = {0,0,0,0}, vh1 = {0,0,0,0}, vl0 = {0,0,0,0}, vl1 = {0,0,0,0};
            if (jg >= 0 && jg < LK) {
                const uint4* ph = (const uint4*)(Kh + ((size_t)(b*LK) + jg)*Dm + hoff + c16);
                const uint4* pl = (const uint4*)(Kl + ((size_t)(b*LK) + jg)*Dm + hoff + c16);
                kh0 = ph[0]; kh1 = ph[1]; kl0 = pl[0]; kl1 = pl[1];
                ph = (const uint4*)(Vh + ((size_t)(b*LK) + jg)*Dm + hoff + c16);
                pl = (const uint4*)(Vl + ((size_t)(b*LK) + jg)*Dm + hoff + c16);
                vh0 = ph[0]; vh1 = ph[1]; vl0 = pl[0]; vl1 = pl[1];
            }
            *(uint4*)&sKh[row*72 + c16] = kh0; *(uint4*)&sKh[row*72 + c16 + 8] = kh1;
            *(uint4*)&sKl[row*72 + c16] = kl0; *(uint4*)&sKl[row*72 + c16 + 8] = kl1;
            *(uint4*)&sVh[row*72 + c16] = vh0; *(uint4*)&sVh[row*72 + c16 + 8] = vh1;
            *(uint4*)&sVl[row*72 + c16] = vl0; *(uint4*)&sVl[row*72 + c16 + 8] = vl1;
        }
        __syncthreads();

        if (local) {
            int c64 = c*64;
            if (c64 < w*16 - 63 || c64 > w*16 + 143) continue;
        }

        float s[8][4] = {};
        #pragma unroll
        for (int kc = 0; kc < 4; kc++) {
            int ko = kc*16;
            uint32_t offA = ((w*16 + lrow)*72 + ko + lkh)*2;
            uint32_t ah[4], al[4];
            ldmx4(ah, aQh + offA);
            ldmx4(al, aQl + offA);
            #pragma unroll
            for (int ntp = 0; ntp < 4; ntp++) {
                uint32_t offB = ((ntp*16 + lrow)*72 + ko + lkh)*2;
                uint32_t kh4[4], kl4[4];
                ldmx4(kh4, aKh + offB);
                ldmx4(kl4, aKl + offB);
                uint32_t bhf0[2] = { kh4[0], kh4[2] }, bhf1[2] = { kh4[1], kh4[3] };
                uint32_t blf0[2] = { kl4[0], kl4[2] }, blf1[2] = { kl4[1], kl4[3] };
                mma16816(s[ntp*2],   ah, bhf0);
                mma16816(s[ntp*2],   ah, blf0);
                mma16816(s[ntp*2],   al, bhf0);
                mma16816(s[ntp*2+1], ah, bhf1);
                mma16816(s[ntp*2+1], ah, blf1);
                mma16816(s[ntp*2+1], al, bhf1);
            }
        }

        float m0 = -INFINITY, m1 = -INFINITY;
        #pragma unroll
        for (int nt = 0; nt < 8; nt++) {
            int jc0 = jbase + nt*8 + qc;
            int jc1 = jc0 + 1;
            #pragma unroll
            for (int rg = 0; rg < 4; rg++) s[nt][rg] *= 0.125f;
            bool ok00 = true, ok01 = true, ok10 = true, ok11 = true;
            if (local) {
                ok00 = (jc0 >= 0) & (jc0 < LK) & (jc0 >= ir0-64) & (jc0 <= ir0+64);
                ok01 = (jc1 >= 0) & (jc1 < LK) & (jc1 >= ir0-64) & (jc1 <= ir0+64);
                ok10 = (jc0 >= 0) & (jc0 < LK) & (jc0 >= ir1-64) & (jc0 <= ir1+64);
                ok11 = (jc1 >= 0) & (jc1 < LK) & (jc1 >= ir1-64) & (jc1 <= ir1+64);
            }
            if (ok00) m0 = fmaxf(m0, s[nt][0]);
            if (ok01) m0 = fmaxf(m0, s[nt][1]);
            if (ok10) m1 = fmaxf(m1, s[nt][2]);
            if (ok11) m1 = fmaxf(m1, s[nt][3]);
        }
        m0 = fmaxf(m0, __shfl_xor_sync(0xFFFFFFFFu, m0, 1));
        m0 = fmaxf(m0, __shfl_xor_sync(0xFFFFFFFFu, m0, 2));
        m1 = fmaxf(m1, __shfl_xor_sync(0xFFFFFFFFu, m1, 1));
        m1 = fmaxf(m1, __shfl_xor_sync(0xFFFFFFFFu, m1, 2));
        float mn0 = fmaxf(mr0, m0), mn1 = fmaxf(mr1, m1);
        float cf0 = (mn0 == -INFINITY) ? 1.f : __expf(mr0 - mn0);
        float cf1 = (mn1 == -INFINITY) ? 1.f : __expf(mr1 - mn1);
        mr0 = mn0; mr1 = mn1;

        float ps0 = 0.f, ps1 = 0.f;
        #pragma unroll
        for (int nt = 0; nt < 8; nt++) {
            int jc0 = jbase + nt*8 + qc;
            int jc1 = jc0 + 1;
            bool ok00 = true, ok01 = true, ok10 = true, ok11 = true;
            if (local) {
                ok00 = (jc0 >= 0) & (jc0 < LK) & (jc0 >= ir0-64) & (jc0 <= ir0+64);
                ok01 = (jc1 >= 0) & (jc1 < LK) & (jc1 >= ir0-64) & (jc1 <= ir0+64);
                ok10 = (jc0 >= 0) & (jc0 < LK) & (jc0 >= ir1-64) & (jc0 <= ir1+64);
                ok11 = (jc1 >= 0) & (jc1 < LK) & (jc1 >= ir1-64) & (jc1 <= ir1+64);
            }
            s[nt][0] = ok00 ? __expf(s[nt][0] - mn0) : 0.f;
            s[nt][1] = ok01 ? __expf(s[nt][1] - mn0) : 0.f;
            s[nt][2] = ok10 ? __expf(s[nt][2] - mn1) : 0.f;
            s[nt][3] = ok11 ? __expf(s[nt][3] - mn1) : 0.f;
            ps0 += s[nt][0] + s[nt][1];
            ps1 += s[nt][2] + s[nt][3];
        }
        ps0 += __shfl_xor_sync(0xFFFFFFFFu, ps0, 1); ps0 += __shfl_xor_sync(0xFFFFFFFFu, ps0, 2);
        ps1 += __shfl_xor_sync(0xFFFFFFFFu, ps1, 1); ps1 += __shfl_xor_sync(0xFFFFFFFFu, ps1, 2);
        lr0 = lr0*cf0 + ps0;
        lr1 = lr1*cf1 + ps1;

        #pragma unroll
        for (int ntd = 0; ntd < 8; ntd++) {
            accO[ntd][0] *= cf0; accO[ntd][1] *= cf0;
            accO[ntd][2] *= cf1; accO[ntd][3] *= cf1;
        }

        #pragma unroll
        for (int kch = 0; kch < 4; kch++) {
            int nt0 = kch*2, nt1 = kch*2 + 1;
            uint32_t pah[4], pal[4];
            {
                float p00 = s[nt0][0], p01 = s[nt0][1], p02 = s[nt0][2], p03 = s[nt0][3];
                float p10 = s[nt1][0], p11 = s[nt1][1], p12 = s[nt1][2], p13 = s[nt1][3];
                pah[0] = packbf(p00, p01); pah[1] = packbf(p02, p03);
                pah[2] = packbf(p10, p11); pah[3] = packbf(p12, p13);
                float q00 = p00 - __bfloat162float(__float2bfloat16(p00));
                float q01 = p01 - __bfloat162float(__float2bfloat16(p01));
                float q02 = p02 - __bfloat162float(__float2bfloat16(p02));
                float q03 = p03 - __bfloat162float(__float2bfloat16(p03));
                float q10 = p10 - __bfloat162float(__float2bfloat16(p10));
                float q11 = p11 - __bfloat162float(__float2bfloat16(p11));
                float q12 = p12 - __bfloat162float(__float2bfloat16(p12));
                float q13 = p13 - __bfloat162float(__float2bfloat16(p13));
                pal[0] = packbf(q00, q01); pal[1] = packbf(q02, q03);
                pal[2] = packbf(q10, q11); pal[3] = packbf(q12, q13);
            }
            const int jo = kch*16;
            #pragma unroll
            for (int ntp = 0; ntp < 4; ntp++) {
                uint32_t offV = ((jo + lrow)*72 + ntp*16 + lkh)*2;
                uint32_t vh4[4], vl4[4];
                ldmx4t(vh4, aVh + offV);
                ldmx4t(vl4, aVl + offV);
                mma16816(accO[ntp*2],   pah, &vh4[0]);
                mma16816(accO[ntp*2],   pal, &vh4[0]);
                mma16816(accO[ntp*2],   pah, &vl4[0]);
                mma16816(accO[ntp*2+1], pah, &vh4[2]);
                mma16816(accO[ntp*2+1], pal, &vh4[2]);
                mma16816(accO[ntp*2+1], pah, &vl4[2]);
            }
        }
    }

    float inv0 = 1.0f/lr0, inv1 = 1.0f/lr1;
    #pragma unroll
    for (int ntd = 0; ntd < 8; ntd++) {
        *(float2*)&Out[((size_t)(b*Ls) + ir0)*Dm + hoff + ntd*8 + qc] =
            make_float2(accO[ntd][0]*inv0, accO[ntd][1]*inv0);
        *(float2*)&Out[((size_t)(b*Ls) + ir1)*Dm + hoff + ntd*8 + qc] =
            make_float2(accO[ntd][2]*inv1, accO[ntd][3]*inv1);
    }
}

// ---------------- combine + split comb ----------------
__global__ void combine_kernel(const float* __restrict__ pm)
{
    float a0 = pm[0], a1 = pm[1], a2 = pm[2];
    float mx = fmaxf(a0, fmaxf(a1, a2));
    float e0 = expf(a0-mx), e1 = expf(a1-mx), e2 = expf(a2-mx);
    float den = e0+e1+e2;
    float pw0 = e0/den, pw1 = e1/den;
    int e = blockIdx.x*blockDim.x + threadIdx.x;
    float v = pw0*g_outg[e] + pw1*g_outl[e];
    g_comb[e] = v;
    bsplit(v, g_combh[e], g_combl[e]);
}

// ---------------- selection path ----------------
__global__ void attns_kernel(const float* __restrict__ pm)
{
    __shared__ float sc[Ls];
    __shared__ float qs[64];
    __shared__ float red[256];
    int blk = blockIdx.x;
    int bh  = blk / NSEL, si = blk % NSEL;
    int b = bh >> 3, h = bh & 7;
    int qi = g_selidx[bh*NSEL + si];
    int t = threadIdx.x;

    if (t < 16) {
        float4 v = *(const float4*)&g_q[((size_t)(b*Ls) + qi)*Dm + h*HDim + t*4];
        *(float4*)&qs[t*4] = v;
    }
    __syncthreads();

    const float* kb = g_k + ((size_t)(b*Ls))*Dm + h*HDim;
    for (int jj = 0; jj < 8; jj++) {
        int j = t*8 + jj;
        const float4* kr = (const float4*)&kb[(size_t)j*Dm];
        float dot = 0.f;
        #pragma unroll
        for (int d4 = 0; d4 < 16; d4++) {
            float4 kv = kr[d4];
            dot = fmaf(qs[d4*4+0], kv.x, dot);
            dot = fmaf(qs[d4*4+1], kv.y, dot);
            dot = fmaf(qs[d4*4+2], kv.z, dot);
            dot = fmaf(qs[d4*4+3], kv.w, dot);
        }
        sc[j] = dot * 0.125f;
    }
    __syncthreads();

    float m = -INFINITY;
    for (int j = t; j < Ls; j += 256) m = fmaxf(m, sc[j]);
    red[t] = m; __syncthreads();
    for (int s2 = 128; s2; s2 >>= 1) { if (t < s2) red[t] = fmaxf(red[t], red[t+s2]); __syncthreads(); }
    m = red[0]; __syncthreads();

    float s = 0.f;
    for (int j = t; j < Ls; j += 256) { float e = __expf(sc[j]-m); sc[j] = e; s += e; }
    red[t] = s; __syncthreads();
    for (int s2 = 128; s2; s2 >>= 1) { if (t < s2) red[t] += red[t+s2]; __syncthreads(); }
    s = red[0]; __syncthreads();

    int d = t & 63, qtr = t >> 6;
    const float* vb = g_v + ((size_t)b*Ls)*Dm + h*HDim + d;
    float acc = 0.f;
    for (int j = qtr*512; j < qtr*512 + 512; j++)
        acc = fmaf(sc[j], vb[(size_t)j*Dm], acc);
    red[t] = acc; __syncthreads();

    if (t < 64) {
        float tot = red[t] + red[t+64] + red[t+128] + red[t+192];
        float a0 = pm[0], a1 = pm[1], a2 = pm[2];
        float mx = fmaxf(a0, fmaxf(a1, a2));
        float e0 = expf(a0-mx), e1 = expf(a1-mx), e2 = expf(a2-mx);
        float pw2 = e2/(e0+e1+e2);
        size_t idx = ((size_t)b*Ls + qi)*Dm + h*HDim + t;
        float nv = g_comb[idx] + pw2 * tot / s;
        g_comb[idx] = nv;
        bsplit(nv, g_combh[idx], g_combl[idx]);
    }
}

// ---------------- launch ----------------
extern "C" void kernel_launch(void* const* d_in, const int* in_sizes, int n_in,
                              void* d_out, int out_size)
{
    const float* query = (const float*)d_in[0];
    const float* keyi  = (const float*)d_in[1];
    const float* vali  = (const float*)d_in[2];
    const float* Wq = (const float*)d_in[3];  const float* bq = (const float*)d_in[4];
    const float* Wk = (const float*)d_in[5];  const float* bk = (const float*)d_in[6];
    const float* Wv = (const float*)d_in[7];  const float* bv = (const float*)d_in[8];
    const float* Wo = (const float*)d_in[9];  const float* bo = (const float*)d_in[10];
    const float* Wc1 = (const float*)d_in[11]; const float* bc1 = (const float*)d_in[12];
    const float* Wc2 = (const float*)d_in[13]; const float* bc2 = (const float*)d_in[14];
    const float* pm  = (const float*)d_in[15];

    __nv_bfloat16 *kcpreh, *kcprel, *hidh, *hidl, *combh, *combl, *wth, *wtl;
    __nv_bfloat16 *qh, *ql, *kh, *kl, *vh, *vl, *kch, *kcl, *vch, *vcl;
    float *mlppart;
    cudaGetSymbolAddress((void**)&kcpreh, g_kcpreh);
    cudaGetSymbolAddress((void**)&kcprel, g_kcprel);
    cudaGetSymbolAddress((void**)&hidh,  g_hidh);
    cudaGetSymbolAddress((void**)&hidl,  g_hidl);
    cudaGetSymbolAddress((void**)&combh, g_combh);
    cudaGetSymbolAddress((void**)&combl, g_combl);
    cudaGetSymbolAddress((void**)&wth,   g_wth);
    cudaGetSymbolAddress((void**)&wtl,   g_wtl);
    cudaGetSymbolAddress((void**)&qh,    g_qh);
    cudaGetSymbolAddress((void**)&ql,    g_ql);
    cudaGetSymbolAddress((void**)&kh,    g_kh);
    cudaGetSymbolAddress((void**)&kl,    g_kl);
    cudaGetSymbolAddress((void**)&vh,    g_vh);
    cudaGetSymbolAddress((void**)&vl,    g_vl);
    cudaGetSymbolAddress((void**)&kch,   g_kch);
    cudaGetSymbolAddress((void**)&kcl,   g_kcl);
    cudaGetSymbolAddress((void**)&vch,   g_vch);
    cudaGetSymbolAddress((void**)&vcl,   g_vcl);
    cudaGetSymbolAddress((void**)&mlppart, g_mlppart);

    float *outg, *outl;
    cudaGetSymbolAddress((void**)&outg,  g_outg);
    cudaGetSymbolAddress((void**)&outl,  g_outl);

    const int FLASH_SMEM = (2*128*72 + 4*64*72)*2;   // 73728
    const int SCORES_SMEM = 4*128*72*2;              // 73728
    cudaFuncSetAttribute(flash_mma_kernel, cudaFuncAttributeMaxDynamicSharedMemorySize, FLASH_SMEM);
    cudaFuncSetAttribute(scores_stats_mma_kernel, cudaFuncAttributeMaxDynamicSharedMemorySize, SCORES_SMEM);

    // prep + projections
    split_w6_kernel<<<dim3(16,16,6), dim3(32,8)>>>(Wq, Wk, Wv, Wo, Wc1, Wc2);
    proj3_mma_kernel<<<dim3(4,32,3), 256>>>(query, keyi, vali, bq, bk, bv);

    // compression + MLP (split-K=4 GEMMs: 512 blocks each, measured 18us)
    compress_kernel<<<512, 256>>>();
    mma_gemm64_sk_kernel<<<dim3(8,16,4), 128>>>(kcpreh, kcprel, wth + 4*(size_t)Dm*Dm, wtl + 4*(size_t)Dm*Dm,
                                                mlppart, Dm, Dm);
    mlpreduce_kernel<<<(Bb*LcC*Dm)/512, 256>>>(bc1, 1, hidh, hidl);
    mma_gemm64_sk_kernel<<<dim3(8,16,4), 128>>>(hidh, hidl, wth + 5*(size_t)Dm*Dm, wtl + 5*(size_t)Dm*Dm,
                                                mlppart, Dm, Dm);
    mlpreduce_kernel<<<(Bb*LcC*Dm)/512, 256>>>(bc2, 0, kch, kcl);

    // dense QK^T + fused stats
    scores_stats_mma_kernel<<<dim3(NJT,16,16), 256, SCORES_SMEM>>>(0.125f);
    impfinal_kernel<<<4096, 256>>>();
    topk_kernel<<<Bb*Hh, 256>>>();

    // attention paths
    flash_mma_kernel<<<dim3(16,16,2), 256, FLASH_SMEM>>>(
        qh, ql, kh, kl, vh, vl, kch, kcl, vch, vcl, outl, outg);

    // mix + selection
    combine_kernel<<<(Bb*Ls*Dm)/256, 256>>>(pm);
    attns_kernel<<<Bb*Hh*NSEL, 256>>>(pm);

    // output projection (64x64 deep-pipelined, 512 blocks)
    mma_gemm64_kernel<<<dim3(8,64), 128>>>(combh, combl, wth + 3*(size_t)Dm*Dm, wtl + 3*(size_t)Dm*Dm,
                                           bo, (float*)d_out, nullptr, nullptr, Dm, Dm, 0);
}